// round 4
// baseline (speedup 1.0000x reference)
#include <cuda_runtime.h>
#include <cuda_bf16.h>
#include <cstdint>
#include <math.h>

// ---------------------------------------------------------------------------
// RWKV forward. GEMMs: legacy mma.sync bf16 hi/lo 3-product split, fp32 accum.
// Weights pre-converted to bf16 h/l once per launch; activations produced as
// bf16 h/l by LN / epilogues / WKV. GEMM mainloop is pure bf16 + cp.async.
// ---------------------------------------------------------------------------

#define E_DIM   1024
#define FOUR_E  4096
#define D_IN    512
#define BTOK    4096
#define T_LEN   1024
#define BATCH   4
#define NLAYER  11
#define NCHUNK  16
#define CHLEN   64

// ---------------- device-global scratch (no allocation allowed) ------------
#define WBUF_ELEMS 159907840ull
__device__ __nv_bfloat16 g_wh[WBUF_ELEMS];
__device__ __nv_bfloat16 g_wl[WBUF_ELEMS];

__device__ __nv_bfloat16 g_xnh[BTOK * E_DIM],  g_xnl[BTOK * E_DIM];
__device__ __nv_bfloat16 g_hbh[BTOK * FOUR_E], g_hbl[BTOK * FOUR_E];
__device__ __nv_bfloat16 g_yh [BTOK * E_DIM],  g_yl [BTOK * E_DIM];

__device__ float g_res[BTOK * E_DIM];
__device__ float g_tmp[BTOK * E_DIM];
__device__ float g_k  [BTOK * E_DIM];
__device__ float g_r  [BTOK * E_DIM];
__device__ float g_st [BATCH * NCHUNK * 3 * E_DIM];

// ---------------------------------------------------------------------------
// helpers
// ---------------------------------------------------------------------------
__device__ __forceinline__ uint32_t smem_u32(const void* p) {
    uint32_t a;
    asm("{ .reg .u64 t; cvta.to.shared.u64 t, %1; cvt.u32.u64 %0, t; }" : "=r"(a) : "l"(p));
    return a;
}
__device__ __forceinline__ void ldm_x4(uint32_t* r, uint32_t addr) {
    asm volatile("ldmatrix.sync.aligned.m8n8.x4.shared.b16 {%0,%1,%2,%3}, [%4];"
        : "=r"(r[0]), "=r"(r[1]), "=r"(r[2]), "=r"(r[3]) : "r"(addr));
}
__device__ __forceinline__ void mma_bf16(float* d, const uint32_t* a, uint32_t b0, uint32_t b1) {
    asm volatile("mma.sync.aligned.m16n8k16.row.col.f32.bf16.bf16.f32 "
        "{%0,%1,%2,%3}, {%4,%5,%6,%7}, {%8,%9}, {%0,%1,%2,%3};"
        : "+f"(d[0]), "+f"(d[1]), "+f"(d[2]), "+f"(d[3])
        : "r"(a[0]), "r"(a[1]), "r"(a[2]), "r"(a[3]), "r"(b0), "r"(b1));
}
__device__ __forceinline__ void cp16(uint32_t s, const void* g) {
    asm volatile("cp.async.cg.shared.global [%0], [%1], 16;" :: "r"(s), "l"(g));
}
__device__ __forceinline__ void cp_commit() {
    asm volatile("cp.async.commit_group;" ::: "memory");
}
template <int N> __device__ __forceinline__ void cp_wait() {
    asm volatile("cp.async.wait_group %0;" :: "n"(N) : "memory");
}
// float2 -> truncated-hi bf16x2 + residual-lo bf16x2
__device__ __forceinline__ void split2(float2 v, uint32_t& h, uint32_t& l) {
    uint32_t bx = __float_as_uint(v.x), by = __float_as_uint(v.y);
    h = __byte_perm(bx, by, 0x7632);
    float lx = v.x - __uint_as_float(bx & 0xFFFF0000u);
    float ly = v.y - __uint_as_float(by & 0xFFFF0000u);
    asm("cvt.rn.bf16x2.f32 %0, %1, %2;" : "=r"(l) : "f"(ly), "f"(lx));
}
__device__ __forceinline__ void split4(float4 v, uint32_t& h01, uint32_t& h23,
                                       uint32_t& l01, uint32_t& l23) {
    split2(make_float2(v.x, v.y), h01, l01);
    split2(make_float2(v.z, v.w), h23, l23);
}

// ---------------------------------------------------------------------------
// weight/input conversion: fp32 -> (hi bf16 trunc, lo bf16 residual)
// ---------------------------------------------------------------------------
__global__ void convert_hl(const float4* __restrict__ src,
                           uint2* __restrict__ h, uint2* __restrict__ l, int n4)
{
    int i = blockIdx.x * blockDim.x + threadIdx.x;
    if (i >= n4) return;
    float4 v = src[i];
    uint32_t h01, h23, l01, l23;
    split4(v, h01, h23, l01, l23);
    h[i] = make_uint2(h01, h23);
    l[i] = make_uint2(l01, l23);
}

// ---------------------------------------------------------------------------
// GEMM: C[M,N] = A[M,K] @ W[N,K]^T, bf16 h/l inputs, fp32 epilogue.
// CTA 128x256, 256 threads (8 warps 2m x 4n), warp tile 64x64, 3-stage cp.async.
// ---------------------------------------------------------------------------
#define TM 128
#define TN 256
#define TK 32
#define GT 256
#define STAGES 3

#define ROWB   80
#define OFF_AH 0
#define OFF_AL (128 * ROWB)
#define OFF_BH (2 * 128 * ROWB)
#define OFF_BL (2 * 128 * ROWB + 256 * ROWB)
#define STAGE_SZ (2 * 128 * ROWB + 2 * 256 * ROWB)   // 61440
#define GEMM_SMEM (STAGES * STAGE_SZ)                // 184320

#define EPI_NONE   0
#define EPI_BIAS   1
#define EPI_RELUSQ 2
#define EPI_ADD    3
#define EPI_CMIX   4

template <int EPI>
__global__ __launch_bounds__(GT, 1)
void gemm_bf(const __nv_bfloat16* __restrict__ Ah, const __nv_bfloat16* __restrict__ Al,
             const __nv_bfloat16* __restrict__ Bh, const __nv_bfloat16* __restrict__ Bl,
             float* __restrict__ C, int M, int N, int K,
             const float* __restrict__ bias,
             const float* __restrict__ Cin,
             const float* __restrict__ Rg,
             __nv_bfloat16* __restrict__ Oh, __nv_bfloat16* __restrict__ Ol)
{
    extern __shared__ char smem[];
    const uint32_t sbase = smem_u32(smem);
    const int tid  = threadIdx.x;
    const int lane = tid & 31;
    const int wid  = tid >> 5;
    const int wm   = wid & 1;    // 2 warps in m
    const int wn   = wid >> 1;   // 4 warps in n
    const int bm   = blockIdx.y * TM;
    const int bn   = blockIdx.x * TN;

    const int lrow  = lane & 15;
    const int lchun = lane >> 4;

    float acc[4][8][4];
#pragma unroll
    for (int i = 0; i < 4; i++)
#pragma unroll
        for (int j = 0; j < 8; j++)
#pragma unroll
            for (int q = 0; q < 4; q++) acc[i][j][q] = 0.f;

    const int S = K / TK;

    auto issue = [&](int s, int buf) {
        const uint32_t sb = sbase + buf * STAGE_SZ;
        const int k0 = s * TK;
        // A tiles (h + l): 128 rows x 4 segs of 16B, 2 iters/thread
#pragma unroll
        for (int i = 0; i < 2; i++) {
            int idx = tid + i * GT;
            int row = idx >> 2, seg = idx & 3;
            uint32_t sa = sb + OFF_AH + row * ROWB + seg * 16;
            size_t go = (size_t)(bm + row) * K + k0 + seg * 8;
            cp16(sa, Ah + go);
            cp16(sa + (OFF_AL - OFF_AH), Al + go);
        }
        // B tiles (h + l): 256 rows x 4 segs, 4 iters/thread
#pragma unroll
        for (int i = 0; i < 4; i++) {
            int idx = tid + i * GT;
            int row = idx >> 2, seg = idx & 3;
            uint32_t sa = sb + OFF_BH + row * ROWB + seg * 16;
            size_t go = (size_t)(bn + row) * K + k0 + seg * 8;
            cp16(sa, Bh + go);
            cp16(sa + (OFF_BL - OFF_BH), Bl + go);
        }
    };

    issue(0, 0); cp_commit();
    issue(1, 1); cp_commit();

    for (int s = 0; s < S; s++) {
        const int buf = s % STAGES;
        if (s + 2 < S) issue(s + 2, (s + 2) % STAGES);
        cp_commit();
        cp_wait<2>();
        __syncthreads();

        const uint32_t sb = sbase + buf * STAGE_SZ;
#pragma unroll
        for (int kk = 0; kk < 2; kk++) {
            const uint32_t koff = (uint32_t)((kk * 2 + lchun) * 16);
            uint32_t bh[4][4], bl[4][4];
#pragma unroll
            for (int bt = 0; bt < 4; bt++) {
                uint32_t ba = sb + OFF_BH + (uint32_t)((wn * 64 + bt * 16 + lrow) * ROWB) + koff;
                ldm_x4(bh[bt], ba);
                ldm_x4(bl[bt], ba + (OFF_BL - OFF_BH));
            }
#pragma unroll
            for (int mt = 0; mt < 4; mt++) {
                uint32_t ah[4], al[4];
                uint32_t aa = sb + OFF_AH + (uint32_t)((wm * 64 + mt * 16 + lrow) * ROWB) + koff;
                ldm_x4(ah, aa);
                ldm_x4(al, aa + (OFF_AL - OFF_AH));
#pragma unroll
                for (int bt = 0; bt < 4; bt++)
#pragma unroll
                    for (int j = 0; j < 2; j++) {
                        const int nt = bt * 2 + j;
                        mma_bf16(acc[mt][nt], ah, bh[bt][j], bh[bt][2 + j]);
                        mma_bf16(acc[mt][nt], ah, bl[bt][j], bl[bt][2 + j]);
                        mma_bf16(acc[mt][nt], al, bh[bt][j], bh[bt][2 + j]);
                    }
            }
        }
        __syncthreads();
    }

    // epilogue
#pragma unroll
    for (int mt = 0; mt < 4; mt++)
#pragma unroll
        for (int nt = 0; nt < 8; nt++) {
            const int row0 = bm + wm * 64 + mt * 16 + (lane >> 2);
            const int col  = bn + wn * 64 + (nt >> 1) * 16 + (nt & 1) * 8 + (lane & 3) * 2;
#pragma unroll
            for (int h = 0; h < 2; h++) {
                const int r = row0 + h * 8;
                const size_t idx = (size_t)r * N + col;
                float2 v = make_float2(acc[mt][nt][2 * h + 0], acc[mt][nt][2 * h + 1]);
                if (EPI == EPI_BIAS) {
                    float2 bb = *reinterpret_cast<const float2*>(bias + col);
                    v.x += bb.x; v.y += bb.y;
                    *reinterpret_cast<float2*>(C + idx) = v;
                }
                if (EPI == EPI_NONE) {
                    *reinterpret_cast<float2*>(C + idx) = v;
                }
                if (EPI == EPI_RELUSQ) {
                    v.x = v.x > 0.f ? v.x * v.x : 0.f;
                    v.y = v.y > 0.f ? v.y * v.y : 0.f;
                    uint32_t hh, ll;
                    split2(v, hh, ll);
                    *reinterpret_cast<uint32_t*>(Oh + idx) = hh;
                    *reinterpret_cast<uint32_t*>(Ol + idx) = ll;
                }
                if (EPI == EPI_ADD) {
                    float2 ci = *reinterpret_cast<const float2*>(Cin + idx);
                    v.x += ci.x; v.y += ci.y;
                    *reinterpret_cast<float2*>(C + idx) = v;
                }
                if (EPI == EPI_CMIX) {
                    float2 ci = *reinterpret_cast<const float2*>(Cin + idx);
                    float2 rr = *reinterpret_cast<const float2*>(Rg + idx);
                    v.x = ci.x + v.x * (1.f / (1.f + expf(-rr.x)));
                    v.y = ci.y + v.y * (1.f / (1.f + expf(-rr.y)));
                    *reinterpret_cast<float2*>(C + idx) = v;
                }
            }
        }
}

// ---------------------------------------------------------------------------
// LayerNorm over E=1024; optional fp32 out and/or bf16 h/l out.
// ---------------------------------------------------------------------------
__global__ __launch_bounds__(256)
void ln_kernel(const float* __restrict__ x, float* __restrict__ o,
               __nv_bfloat16* __restrict__ oh, __nv_bfloat16* __restrict__ ol,
               const float* __restrict__ g, const float* __restrict__ b)
{
    __shared__ float sm[18];
    const int row = blockIdx.x;
    const int t   = threadIdx.x;
    float4 v = reinterpret_cast<const float4*>(x + (size_t)row * E_DIM)[t];
    float s  = v.x + v.y + v.z + v.w;
    float ss = v.x * v.x + v.y * v.y + v.z * v.z + v.w * v.w;
#pragma unroll
    for (int off = 16; off > 0; off >>= 1) {
        s  += __shfl_xor_sync(0xffffffffu, s, off);
        ss += __shfl_xor_sync(0xffffffffu, ss, off);
    }
    const int wp = t >> 5, lane = t & 31;
    if (lane == 0) { sm[wp] = s; sm[8 + wp] = ss; }
    __syncthreads();
    if (t < 32) {
        s  = (t < 8) ? sm[t]     : 0.f;
        ss = (t < 8) ? sm[8 + t] : 0.f;
#pragma unroll
        for (int off = 4; off > 0; off >>= 1) {
            s  += __shfl_xor_sync(0xffffffffu, s, off);
            ss += __shfl_xor_sync(0xffffffffu, ss, off);
        }
        if (t == 0) {
            float mean = s * (1.f / E_DIM);
            float var  = ss * (1.f / E_DIM) - mean * mean;
            sm[16] = mean;
            sm[17] = rsqrtf(var + 1e-5f);
        }
    }
    __syncthreads();
    const float mean = sm[16], inv = sm[17];
    float4 gg = reinterpret_cast<const float4*>(g)[t];
    float4 bb = reinterpret_cast<const float4*>(b)[t];
    float4 ov;
    ov.x = (v.x - mean) * inv * gg.x + bb.x;
    ov.y = (v.y - mean) * inv * gg.y + bb.y;
    ov.z = (v.z - mean) * inv * gg.z + bb.z;
    ov.w = (v.w - mean) * inv * gg.w + bb.w;
    if (o) reinterpret_cast<float4*>(o + (size_t)row * E_DIM)[t] = ov;
    if (oh) {
        uint32_t h01, h23, l01, l23;
        split4(ov, h01, h23, l01, l23);
        reinterpret_cast<uint2*>(oh + (size_t)row * E_DIM)[t] = make_uint2(h01, h23);
        reinterpret_cast<uint2*>(ol + (size_t)row * E_DIM)[t] = make_uint2(l01, l23);
    }
}

// ---------------------------------------------------------------------------
// WKV recurrence, exact chunked 2-pass scan. pass2 emits sigmoid(r)*wkv as
// bf16 h/l (input to the Wo GEMM).
// ---------------------------------------------------------------------------
__global__ __launch_bounds__(128)
void wkv_pass1(const float* __restrict__ k, const float* __restrict__ v,
               const float* __restrict__ decay, float* __restrict__ st)
{
    const int e = blockIdx.x * blockDim.x + threadIdx.x;
    const int c = blockIdx.y, b = blockIdx.z;
    const float w = -expf(decay[e]);
    float aa = 0.f, bb = 0.f, pp = -1e38f;
    const size_t base = ((size_t)b * T_LEN + (size_t)c * CHLEN) * E_DIM + e;
    const float* kp = k + base;
    const float* vp = v + base;
#pragma unroll 4
    for (int t = 0; t < CHLEN; t++) {
        float kt = kp[(size_t)t * E_DIM];
        float vt = vp[(size_t)t * E_DIM];
        float ww = pp + w;
        float p  = fmaxf(ww, kt);
        float e1 = expf(ww - p);
        float e2 = expf(kt - p);
        aa = e1 * aa + e2 * vt;
        bb = e1 * bb + e2;
        pp = p;
    }
    float* s = st + ((size_t)(b * NCHUNK + c) * 3) * E_DIM + e;
    s[0] = aa; s[E_DIM] = bb; s[2 * E_DIM] = pp;
}

__global__ __launch_bounds__(128)
void wkv_pass2(const float* __restrict__ k, const float* __restrict__ v,
               const float* __restrict__ decay, const float* __restrict__ first,
               const float* __restrict__ st,
               __nv_bfloat16* __restrict__ yh, __nv_bfloat16* __restrict__ yl)
{
    const int e = blockIdx.x * blockDim.x + threadIdx.x;
    const int c = blockIdx.y, b = blockIdx.z;
    const float w = -expf(decay[e]);
    const float u = first[e];
    float aa = 0.f, bb = 0.f, pp = -1e38f;
    for (int j = 0; j < c; j++) {
        const float* s = st + ((size_t)(b * NCHUNK + j) * 3) * E_DIM + e;
        float pd = pp + (float)CHLEN * w;
        float a2 = s[0], b2 = s[E_DIM], p2 = s[2 * E_DIM];
        float p  = fmaxf(pd, p2);
        float e1 = expf(pd - p), e2 = expf(p2 - p);
        aa = e1 * aa + e2 * a2;
        bb = e1 * bb + e2 * b2;
        pp = p;
    }
    const size_t base = ((size_t)b * T_LEN + (size_t)c * CHLEN) * E_DIM + e;
    const float* kp = k + base;
    const float* vp = v + base;
    for (int t = 0; t < CHLEN; t++) {
        float kt = kp[(size_t)t * E_DIM];
        float vt = vp[(size_t)t * E_DIM];   // v == r in this model
        float ww = u + kt;
        float p  = fmaxf(pp, ww);
        float e1 = expf(pp - p), e2 = expf(ww - p);
        float yt = (e1 * aa + e2 * vt) / (e1 * bb + e2);
        float ys = yt * (1.f / (1.f + expf(-vt)));
        uint32_t bits = __float_as_uint(ys);
        const size_t off = base + (size_t)t * E_DIM;
        yh[off] = __ushort_as_bfloat16((unsigned short)(bits >> 16));
        yl[off] = __float2bfloat16_rn(ys - __uint_as_float(bits & 0xFFFF0000u));
        float ww2 = pp + w;
        float p2  = fmaxf(ww2, kt);
        e1 = expf(ww2 - p2); e2 = expf(kt - p2);
        aa = e1 * aa + e2 * vt;
        bb = e1 * bb + e2;
        pp = p2;
    }
}

// ---------------------------------------------------------------------------
// Host orchestration
// ---------------------------------------------------------------------------
static void set_smem_attrs() {
    cudaFuncSetAttribute(gemm_bf<EPI_NONE>,   cudaFuncAttributeMaxDynamicSharedMemorySize, GEMM_SMEM);
    cudaFuncSetAttribute(gemm_bf<EPI_BIAS>,   cudaFuncAttributeMaxDynamicSharedMemorySize, GEMM_SMEM);
    cudaFuncSetAttribute(gemm_bf<EPI_RELUSQ>, cudaFuncAttributeMaxDynamicSharedMemorySize, GEMM_SMEM);
    cudaFuncSetAttribute(gemm_bf<EPI_ADD>,    cudaFuncAttributeMaxDynamicSharedMemorySize, GEMM_SMEM);
    cudaFuncSetAttribute(gemm_bf<EPI_CMIX>,   cudaFuncAttributeMaxDynamicSharedMemorySize, GEMM_SMEM);
}

extern "C" void kernel_launch(void* const* d_in, const int* in_sizes, int n_in,
                              void* d_out, int out_size)
{
    const float* inp    = (const float*)d_in[0];
    const float* W_in   = (const float*)d_in[1];
    const float* b_in   = (const float*)d_in[2];
    const float* ln0g   = (const float*)d_in[3];
    const float* ln0b   = (const float*)d_in[4];
    const float* l0ln1g = (const float*)d_in[5];
    const float* l0ln1b = (const float*)d_in[6];
    const float* l0ln2g = (const float*)d_in[7];
    const float* l0ln2b = (const float*)d_in[8];
    const float* l0cmk  = (const float*)d_in[9];
    const float* l0cmv  = (const float*)d_in[10];
    const float* l0cmr  = (const float*)d_in[11];
    const float* l0ffk  = (const float*)d_in[12];
    const float* l0ffv  = (const float*)d_in[13];
    const float* l0ffr  = (const float*)d_in[14];
    const float* tmk    = (const float*)d_in[15];
    const float* tmr    = (const float*)d_in[16];
    const float* tmo    = (const float*)d_in[17];
    const float* tmdec  = (const float*)d_in[18];
    const float* tmfst  = (const float*)d_in[19];
    const float* ln1g   = (const float*)d_in[20];
    const float* ln1b   = (const float*)d_in[21];
    const float* ln2g   = (const float*)d_in[22];
    const float* ln2b   = (const float*)d_in[23];
    const float* ffk    = (const float*)d_in[24];
    const float* ffv    = (const float*)d_in[25];
    const float* ffr    = (const float*)d_in[26];
    const float* outg   = (const float*)d_in[27];
    const float* outb   = (const float*)d_in[28];
    float* out = (float*)d_out;

    set_smem_attrs();

    __nv_bfloat16 *wh, *wl, *xnh, *xnl, *hbh, *hbl, *yh, *yl;
    float *res, *tmp, *kb, *rb, *st;
    cudaGetSymbolAddress((void**)&wh,  g_wh);
    cudaGetSymbolAddress((void**)&wl,  g_wl);
    cudaGetSymbolAddress((void**)&xnh, g_xnh);
    cudaGetSymbolAddress((void**)&xnl, g_xnl);
    cudaGetSymbolAddress((void**)&hbh, g_hbh);
    cudaGetSymbolAddress((void**)&hbl, g_hbl);
    cudaGetSymbolAddress((void**)&yh,  g_yh);
    cudaGetSymbolAddress((void**)&yl,  g_yl);
    cudaGetSymbolAddress((void**)&res, g_res);
    cudaGetSymbolAddress((void**)&tmp, g_tmp);
    cudaGetSymbolAddress((void**)&kb,  g_k);
    cudaGetSymbolAddress((void**)&rb,  g_r);
    cudaGetSymbolAddress((void**)&st,  g_st);

    // ---- pre-convert weights + inputs to bf16 h/l ----
    size_t off = 0;
    auto conv = [&](const float* src, size_t n) -> size_t {
        size_t o = off;
        int n4 = (int)(n / 4);
        convert_hl<<<(n4 + 255) / 256, 256>>>((const float4*)src,
                                              (uint2*)(wh + o), (uint2*)(wl + o), n4);
        off += n;
        return o;
    };
    const size_t o_win  = conv(W_in,  (size_t)E_DIM * D_IN);
    const size_t o_cmk  = conv(l0cmk, (size_t)FOUR_E * E_DIM);
    const size_t o_cmv  = conv(l0cmv, (size_t)E_DIM * FOUR_E);
    const size_t o_cmr  = conv(l0cmr, (size_t)E_DIM * E_DIM);
    const size_t o_lffk = conv(l0ffk, (size_t)FOUR_E * E_DIM);
    const size_t o_lffv = conv(l0ffv, (size_t)E_DIM * FOUR_E);
    const size_t o_lffr = conv(l0ffr, (size_t)E_DIM * E_DIM);
    const size_t o_tmk  = conv(tmk, (size_t)NLAYER * E_DIM * E_DIM);
    const size_t o_tmr  = conv(tmr, (size_t)NLAYER * E_DIM * E_DIM);
    const size_t o_tmo  = conv(tmo, (size_t)NLAYER * E_DIM * E_DIM);
    const size_t o_ffk  = conv(ffk, (size_t)NLAYER * FOUR_E * E_DIM);
    const size_t o_ffv  = conv(ffv, (size_t)NLAYER * E_DIM * FOUR_E);
    const size_t o_ffr  = conv(ffr, (size_t)NLAYER * E_DIM * E_DIM);
    const size_t o_inp  = conv(inp, (size_t)BTOK * D_IN);

    const dim3 gE  (E_DIM  / TN, BTOK / TM);  // (4, 32)
    const dim3 g4E (FOUR_E / TN, BTOK / TM);  // (16, 32)
    const dim3 gWKV(E_DIM / 128, NCHUNK, BATCH);

    // x = inputs @ W_in^T + b_in ; res = LN(x, ln0)
    gemm_bf<EPI_BIAS><<<gE, GT, GEMM_SMEM>>>(wh + o_inp, wl + o_inp, wh + o_win, wl + o_win,
                                             tmp, BTOK, E_DIM, D_IN, b_in, nullptr, nullptr,
                                             nullptr, nullptr);
    ln_kernel<<<BTOK, 256>>>(tmp, res, nullptr, nullptr, ln0g, ln0b);

    auto cmix = [&](const float* lg, const float* lb,
                    size_t ok, size_t ov, size_t orr) {
        ln_kernel<<<BTOK, 256>>>(res, nullptr, xnh, xnl, lg, lb);
        gemm_bf<EPI_RELUSQ><<<g4E, GT, GEMM_SMEM>>>(xnh, xnl, wh + ok, wl + ok,
            nullptr, BTOK, FOUR_E, E_DIM, nullptr, nullptr, nullptr, hbh, hbl);
        gemm_bf<EPI_NONE><<<gE, GT, GEMM_SMEM>>>(xnh, xnl, wh + orr, wl + orr,
            rb, BTOK, E_DIM, E_DIM, nullptr, nullptr, nullptr, nullptr, nullptr);
        gemm_bf<EPI_CMIX><<<gE, GT, GEMM_SMEM>>>(hbh, hbl, wh + ov, wl + ov,
            res, BTOK, E_DIM, FOUR_E, nullptr, res, rb, nullptr, nullptr);
    };

    cmix(l0ln1g, l0ln1b, o_cmk, o_cmv, o_cmr);
    cmix(l0ln2g, l0ln2b, o_lffk, o_lffv, o_lffr);

    for (int l = 0; l < NLAYER; l++) {
        const size_t oEE = (size_t)l * E_DIM * E_DIM;
        const size_t o4E = (size_t)l * FOUR_E * E_DIM;
        const size_t oE  = (size_t)l * E_DIM;

        ln_kernel<<<BTOK, 256>>>(res, nullptr, xnh, xnl, ln1g + oE, ln1b + oE);
        gemm_bf<EPI_NONE><<<gE, GT, GEMM_SMEM>>>(xnh, xnl, wh + o_tmk + oEE, wl + o_tmk + oEE,
            kb, BTOK, E_DIM, E_DIM, nullptr, nullptr, nullptr, nullptr, nullptr);
        gemm_bf<EPI_NONE><<<gE, GT, GEMM_SMEM>>>(xnh, xnl, wh + o_tmr + oEE, wl + o_tmr + oEE,
            rb, BTOK, E_DIM, E_DIM, nullptr, nullptr, nullptr, nullptr, nullptr);
        wkv_pass1<<<gWKV, 128>>>(kb, rb, tmdec + oE, st);
        wkv_pass2<<<gWKV, 128>>>(kb, rb, tmdec + oE, tmfst + oE, st, yh, yl);
        gemm_bf<EPI_ADD><<<gE, GT, GEMM_SMEM>>>(yh, yl, wh + o_tmo + oEE, wl + o_tmo + oEE,
            res, BTOK, E_DIM, E_DIM, nullptr, res, nullptr, nullptr, nullptr);

        ln_kernel<<<BTOK, 256>>>(res, nullptr, xnh, xnl, ln2g + oE, ln2b + oE);
        gemm_bf<EPI_RELUSQ><<<g4E, GT, GEMM_SMEM>>>(xnh, xnl, wh + o_ffk + o4E, wl + o_ffk + o4E,
            nullptr, BTOK, FOUR_E, E_DIM, nullptr, nullptr, nullptr, hbh, hbl);
        gemm_bf<EPI_NONE><<<gE, GT, GEMM_SMEM>>>(xnh, xnl, wh + o_ffr + oEE, wl + o_ffr + oEE,
            rb, BTOK, E_DIM, E_DIM, nullptr, nullptr, nullptr, nullptr, nullptr);
        gemm_bf<EPI_CMIX><<<gE, GT, GEMM_SMEM>>>(hbh, hbl, wh + o_ffv + o4E, wl + o_ffv + o4E,
            res, BTOK, E_DIM, FOUR_E, nullptr, res, rb, nullptr, nullptr);
    }

    ln_kernel<<<BTOK, 256>>>(res, out, nullptr, nullptr, outg, outb);
}

// round 5
// speedup vs baseline: 1.0398x; 1.0398x over previous
#include <cuda_runtime.h>
#include <cuda_bf16.h>
#include <cstdint>
#include <math.h>

// ---------------------------------------------------------------------------
// RWKV forward. GEMMs: legacy mma.sync bf16 hi/lo 3-product split, fp32 accum.
// Weights pre-converted (vectorized) to bf16 h/l; activations produced as
// bf16 h/l by LN / epilogues / WKV. GEMM: 512thr, 128x256x32, 3-stage cp.async.
// ---------------------------------------------------------------------------

#define E_DIM   1024
#define FOUR_E  4096
#define D_IN    512
#define BTOK    4096
#define T_LEN   1024
#define BATCH   4
#define NLAYER  11
#define NCHUNK  16
#define CHLEN   64

// ---------------- device-global scratch (no allocation allowed) ------------
#define WBUF_ELEMS 159907840ull
__device__ __nv_bfloat16 g_wh[WBUF_ELEMS];
__device__ __nv_bfloat16 g_wl[WBUF_ELEMS];

__device__ __nv_bfloat16 g_xnh[BTOK * E_DIM],  g_xnl[BTOK * E_DIM];
__device__ __nv_bfloat16 g_hbh[BTOK * FOUR_E], g_hbl[BTOK * FOUR_E];
__device__ __nv_bfloat16 g_yh [BTOK * E_DIM],  g_yl [BTOK * E_DIM];

__device__ float g_res[BTOK * E_DIM];
__device__ float g_tmp[BTOK * E_DIM];
__device__ float g_k  [BTOK * E_DIM];
__device__ float g_r  [BTOK * E_DIM];
__device__ float g_st [BATCH * NCHUNK * 3 * E_DIM];

// ---------------------------------------------------------------------------
// helpers
// ---------------------------------------------------------------------------
__device__ __forceinline__ uint32_t smem_u32(const void* p) {
    uint32_t a;
    asm("{ .reg .u64 t; cvta.to.shared.u64 t, %1; cvt.u32.u64 %0, t; }" : "=r"(a) : "l"(p));
    return a;
}
__device__ __forceinline__ void ldm_x4(uint32_t* r, uint32_t addr) {
    asm volatile("ldmatrix.sync.aligned.m8n8.x4.shared.b16 {%0,%1,%2,%3}, [%4];"
        : "=r"(r[0]), "=r"(r[1]), "=r"(r[2]), "=r"(r[3]) : "r"(addr));
}
__device__ __forceinline__ void mma_bf16(float* d, const uint32_t* a, uint32_t b0, uint32_t b1) {
    asm volatile("mma.sync.aligned.m16n8k16.row.col.f32.bf16.bf16.f32 "
        "{%0,%1,%2,%3}, {%4,%5,%6,%7}, {%8,%9}, {%0,%1,%2,%3};"
        : "+f"(d[0]), "+f"(d[1]), "+f"(d[2]), "+f"(d[3])
        : "r"(a[0]), "r"(a[1]), "r"(a[2]), "r"(a[3]), "r"(b0), "r"(b1));
}
__device__ __forceinline__ void cp16(uint32_t s, const void* g) {
    asm volatile("cp.async.cg.shared.global [%0], [%1], 16;" :: "r"(s), "l"(g));
}
__device__ __forceinline__ void cp_commit() {
    asm volatile("cp.async.commit_group;" ::: "memory");
}
template <int N> __device__ __forceinline__ void cp_wait() {
    asm volatile("cp.async.wait_group %0;" :: "n"(N) : "memory");
}
// float2 -> truncated-hi bf16x2 + residual-lo bf16x2
__device__ __forceinline__ void split2(float2 v, uint32_t& h, uint32_t& l) {
    uint32_t bx = __float_as_uint(v.x), by = __float_as_uint(v.y);
    h = __byte_perm(bx, by, 0x7632);
    float lx = v.x - __uint_as_float(bx & 0xFFFF0000u);
    float ly = v.y - __uint_as_float(by & 0xFFFF0000u);
    asm("cvt.rn.bf16x2.f32 %0, %1, %2;" : "=r"(l) : "f"(ly), "f"(lx));
}
__device__ __forceinline__ void split4(float4 v, uint32_t& h01, uint32_t& h23,
                                       uint32_t& l01, uint32_t& l23) {
    split2(make_float2(v.x, v.y), h01, l01);
    split2(make_float2(v.z, v.w), h23, l23);
}

// ---------------------------------------------------------------------------
// conversion: fp32 -> (hi bf16 trunc, lo bf16 residual), 8 floats per iter
// ---------------------------------------------------------------------------
__global__ void convert_hl(const float4* __restrict__ src,
                           uint4* __restrict__ h, uint4* __restrict__ l, int n8)
{
    const int stride = gridDim.x * blockDim.x;
    for (int i = blockIdx.x * blockDim.x + threadIdx.x; i < n8; i += stride) {
        float4 v0 = src[2 * i];
        float4 v1 = src[2 * i + 1];
        uint4 hh, ll;
        split4(v0, hh.x, hh.y, ll.x, ll.y);
        split4(v1, hh.z, hh.w, ll.z, ll.w);
        h[i] = hh;
        l[i] = ll;
    }
}

// ---------------------------------------------------------------------------
// GEMM: C[M,N] = A[M,K] @ W[N,K]^T, bf16 h/l inputs, fp32 epilogue.
// CTA 128x256x32, 512 threads (16 warps: 2m x 8n), warp tile 64x32, 3 stages.
// ---------------------------------------------------------------------------
#define TM 128
#define TN 256
#define TK 32
#define GT 512
#define STAGES 3

#define ROWB   80
#define OFF_AH 0
#define OFF_AL (128 * ROWB)
#define OFF_BH (2 * 128 * ROWB)
#define OFF_BL (2 * 128 * ROWB + 256 * ROWB)
#define STAGE_SZ (2 * 128 * ROWB + 2 * 256 * ROWB)   // 61440
#define GEMM_SMEM (STAGES * STAGE_SZ)                // 184320

#define EPI_NONE   0
#define EPI_BIAS   1
#define EPI_RELUSQ 2
#define EPI_ADD    3
#define EPI_CMIX   4

template <int EPI>
__global__ __launch_bounds__(GT, 1)
void gemm_bf(const __nv_bfloat16* __restrict__ Ah, const __nv_bfloat16* __restrict__ Al,
             const __nv_bfloat16* __restrict__ Bh, const __nv_bfloat16* __restrict__ Bl,
             float* __restrict__ C, int M, int N, int K,
             const float* __restrict__ bias,
             const float* __restrict__ Cin,
             const float* __restrict__ Rg,
             __nv_bfloat16* __restrict__ Oh, __nv_bfloat16* __restrict__ Ol)
{
    extern __shared__ char smem[];
    const uint32_t sbase = smem_u32(smem);
    const int tid  = threadIdx.x;
    const int lane = tid & 31;
    const int wid  = tid >> 5;
    const int wm   = wid >> 3;   // 2 warps in m (64 rows each)
    const int wn   = wid & 7;    // 8 warps in n (32 cols each)
    const int bm   = blockIdx.y * TM;
    const int bn   = blockIdx.x * TN;

    const int lrow  = lane & 15;
    const int lchun = lane >> 4;

    float acc[4][4][4];   // [mt 16-row][nt 8-col][frag]
#pragma unroll
    for (int i = 0; i < 4; i++)
#pragma unroll
        for (int j = 0; j < 4; j++)
#pragma unroll
            for (int q = 0; q < 4; q++) acc[i][j][q] = 0.f;

    const int S = K / TK;

    auto issue = [&](int s, int buf) {
        const uint32_t sb = sbase + buf * STAGE_SZ;
        const int k0 = s * TK;
        // A (h+l): 128 rows x 4 segs of 16B -> 512 slots, 1 iter/thread
        {
            int row = tid >> 2, seg = tid & 3;
            uint32_t sa = sb + OFF_AH + row * ROWB + seg * 16;
            size_t go = (size_t)(bm + row) * K + k0 + seg * 8;
            cp16(sa, Ah + go);
            cp16(sa + (OFF_AL - OFF_AH), Al + go);
        }
        // B (h+l): 256 rows x 4 segs -> 1024 slots, 2 iters/thread
#pragma unroll
        for (int i = 0; i < 2; i++) {
            int idx = tid + i * GT;
            int row = idx >> 2, seg = idx & 3;
            uint32_t sa = sb + OFF_BH + row * ROWB + seg * 16;
            size_t go = (size_t)(bn + row) * K + k0 + seg * 8;
            cp16(sa, Bh + go);
            cp16(sa + (OFF_BL - OFF_BH), Bl + go);
        }
    };

    issue(0, 0); cp_commit();
    issue(1, 1); cp_commit();

    for (int s = 0; s < S; s++) {
        const int buf = s % STAGES;
        if (s + 2 < S) issue(s + 2, (s + 2) % STAGES);
        cp_commit();
        cp_wait<2>();
        __syncthreads();

        const uint32_t sb = sbase + buf * STAGE_SZ;
#pragma unroll
        for (int kk = 0; kk < 2; kk++) {
            const uint32_t koff = (uint32_t)((kk * 2 + lchun) * 16);
            // B fragments: 32 cols = 2 ldm tiles (h + l)
            uint32_t bh[2][4], bl[2][4];
#pragma unroll
            for (int bt = 0; bt < 2; bt++) {
                uint32_t ba = sb + OFF_BH + (uint32_t)((wn * 32 + bt * 16 + lrow) * ROWB) + koff;
                ldm_x4(bh[bt], ba);
                ldm_x4(bl[bt], ba + (OFF_BL - OFF_BH));
            }
#pragma unroll
            for (int mt = 0; mt < 4; mt++) {
                uint32_t ah[4], al[4];
                uint32_t aa = sb + OFF_AH + (uint32_t)((wm * 64 + mt * 16 + lrow) * ROWB) + koff;
                ldm_x4(ah, aa);
                ldm_x4(al, aa + (OFF_AL - OFF_AH));
#pragma unroll
                for (int bt = 0; bt < 2; bt++)
#pragma unroll
                    for (int j = 0; j < 2; j++) {
                        const int nt = bt * 2 + j;
                        mma_bf16(acc[mt][nt], ah, bh[bt][j], bh[bt][2 + j]);
                        mma_bf16(acc[mt][nt], ah, bl[bt][j], bl[bt][2 + j]);
                        mma_bf16(acc[mt][nt], al, bh[bt][j], bh[bt][2 + j]);
                    }
            }
        }
        __syncthreads();
    }

    // epilogue
#pragma unroll
    for (int mt = 0; mt < 4; mt++)
#pragma unroll
        for (int nt = 0; nt < 4; nt++) {
            const int row0 = bm + wm * 64 + mt * 16 + (lane >> 2);
            const int col  = bn + wn * 32 + nt * 8 + (lane & 3) * 2;
#pragma unroll
            for (int h = 0; h < 2; h++) {
                const int r = row0 + h * 8;
                const size_t idx = (size_t)r * N + col;
                float2 v = make_float2(acc[mt][nt][2 * h + 0], acc[mt][nt][2 * h + 1]);
                if (EPI == EPI_BIAS) {
                    float2 bb = *reinterpret_cast<const float2*>(bias + col);
                    v.x += bb.x; v.y += bb.y;
                    *reinterpret_cast<float2*>(C + idx) = v;
                }
                if (EPI == EPI_NONE) {
                    *reinterpret_cast<float2*>(C + idx) = v;
                }
                if (EPI == EPI_RELUSQ) {
                    v.x = v.x > 0.f ? v.x * v.x : 0.f;
                    v.y = v.y > 0.f ? v.y * v.y : 0.f;
                    uint32_t hh, ll;
                    split2(v, hh, ll);
                    *reinterpret_cast<uint32_t*>(Oh + idx) = hh;
                    *reinterpret_cast<uint32_t*>(Ol + idx) = ll;
                }
                if (EPI == EPI_ADD) {
                    float2 ci = *reinterpret_cast<const float2*>(Cin + idx);
                    v.x += ci.x; v.y += ci.y;
                    *reinterpret_cast<float2*>(C + idx) = v;
                }
                if (EPI == EPI_CMIX) {
                    float2 ci = *reinterpret_cast<const float2*>(Cin + idx);
                    float2 rr = *reinterpret_cast<const float2*>(Rg + idx);
                    v.x = ci.x + v.x * (1.f / (1.f + expf(-rr.x)));
                    v.y = ci.y + v.y * (1.f / (1.f + expf(-rr.y)));
                    *reinterpret_cast<float2*>(C + idx) = v;
                }
            }
        }
}

// ---------------------------------------------------------------------------
// LayerNorm over E=1024; optional fp32 out and/or bf16 h/l out.
// ---------------------------------------------------------------------------
__global__ __launch_bounds__(256)
void ln_kernel(const float* __restrict__ x, float* __restrict__ o,
               __nv_bfloat16* __restrict__ oh, __nv_bfloat16* __restrict__ ol,
               const float* __restrict__ g, const float* __restrict__ b)
{
    __shared__ float sm[18];
    const int row = blockIdx.x;
    const int t   = threadIdx.x;
    float4 v = reinterpret_cast<const float4*>(x + (size_t)row * E_DIM)[t];
    float s  = v.x + v.y + v.z + v.w;
    float ss = v.x * v.x + v.y * v.y + v.z * v.z + v.w * v.w;
#pragma unroll
    for (int off = 16; off > 0; off >>= 1) {
        s  += __shfl_xor_sync(0xffffffffu, s, off);
        ss += __shfl_xor_sync(0xffffffffu, ss, off);
    }
    const int wp = t >> 5, lane = t & 31;
    if (lane == 0) { sm[wp] = s; sm[8 + wp] = ss; }
    __syncthreads();
    if (t < 32) {
        s  = (t < 8) ? sm[t]     : 0.f;
        ss = (t < 8) ? sm[8 + t] : 0.f;
#pragma unroll
        for (int off = 4; off > 0; off >>= 1) {
            s  += __shfl_xor_sync(0xffffffffu, s, off);
            ss += __shfl_xor_sync(0xffffffffu, ss, off);
        }
        if (t == 0) {
            float mean = s * (1.f / E_DIM);
            float var  = ss * (1.f / E_DIM) - mean * mean;
            sm[16] = mean;
            sm[17] = rsqrtf(var + 1e-5f);
        }
    }
    __syncthreads();
    const float mean = sm[16], inv = sm[17];
    float4 gg = reinterpret_cast<const float4*>(g)[t];
    float4 bb = reinterpret_cast<const float4*>(b)[t];
    float4 ov;
    ov.x = (v.x - mean) * inv * gg.x + bb.x;
    ov.y = (v.y - mean) * inv * gg.y + bb.y;
    ov.z = (v.z - mean) * inv * gg.z + bb.z;
    ov.w = (v.w - mean) * inv * gg.w + bb.w;
    if (o) reinterpret_cast<float4*>(o + (size_t)row * E_DIM)[t] = ov;
    if (oh) {
        uint32_t h01, h23, l01, l23;
        split4(ov, h01, h23, l01, l23);
        reinterpret_cast<uint2*>(oh + (size_t)row * E_DIM)[t] = make_uint2(h01, h23);
        reinterpret_cast<uint2*>(ol + (size_t)row * E_DIM)[t] = make_uint2(l01, l23);
    }
}

// ---------------------------------------------------------------------------
// WKV recurrence, exact chunked 2-pass scan. pass2 emits sigmoid(r)*wkv as
// bf16 h/l (input to the Wo GEMM).
// ---------------------------------------------------------------------------
__global__ __launch_bounds__(128)
void wkv_pass1(const float* __restrict__ k, const float* __restrict__ v,
               const float* __restrict__ decay, float* __restrict__ st)
{
    const int e = blockIdx.x * blockDim.x + threadIdx.x;
    const int c = blockIdx.y, b = blockIdx.z;
    const float w = -expf(decay[e]);
    float aa = 0.f, bb = 0.f, pp = -1e38f;
    const size_t base = ((size_t)b * T_LEN + (size_t)c * CHLEN) * E_DIM + e;
    const float* kp = k + base;
    const float* vp = v + base;
#pragma unroll 4
    for (int t = 0; t < CHLEN; t++) {
        float kt = kp[(size_t)t * E_DIM];
        float vt = vp[(size_t)t * E_DIM];
        float ww = pp + w;
        float p  = fmaxf(ww, kt);
        float e1 = expf(ww - p);
        float e2 = expf(kt - p);
        aa = e1 * aa + e2 * vt;
        bb = e1 * bb + e2;
        pp = p;
    }
    float* s = st + ((size_t)(b * NCHUNK + c) * 3) * E_DIM + e;
    s[0] = aa; s[E_DIM] = bb; s[2 * E_DIM] = pp;
}

__global__ __launch_bounds__(128)
void wkv_pass2(const float* __restrict__ k, const float* __restrict__ v,
               const float* __restrict__ decay, const float* __restrict__ first,
               const float* __restrict__ st,
               __nv_bfloat16* __restrict__ yh, __nv_bfloat16* __restrict__ yl)
{
    const int e = blockIdx.x * blockDim.x + threadIdx.x;
    const int c = blockIdx.y, b = blockIdx.z;
    const float w = -expf(decay[e]);
    const float u = first[e];
    float aa = 0.f, bb = 0.f, pp = -1e38f;
    for (int j = 0; j < c; j++) {
        const float* s = st + ((size_t)(b * NCHUNK + j) * 3) * E_DIM + e;
        float pd = pp + (float)CHLEN * w;
        float a2 = s[0], b2 = s[E_DIM], p2 = s[2 * E_DIM];
        float p  = fmaxf(pd, p2);
        float e1 = expf(pd - p), e2 = expf(p2 - p);
        aa = e1 * aa + e2 * a2;
        bb = e1 * bb + e2 * b2;
        pp = p;
    }
    const size_t base = ((size_t)b * T_LEN + (size_t)c * CHLEN) * E_DIM + e;
    const float* kp = k + base;
    const float* vp = v + base;
    for (int t = 0; t < CHLEN; t++) {
        float kt = kp[(size_t)t * E_DIM];
        float vt = vp[(size_t)t * E_DIM];   // v == r in this model
        float ww = u + kt;
        float p  = fmaxf(pp, ww);
        float e1 = expf(pp - p), e2 = expf(ww - p);
        float yt = (e1 * aa + e2 * vt) / (e1 * bb + e2);
        float ys = yt * (1.f / (1.f + expf(-vt)));
        uint32_t bits = __float_as_uint(ys);
        const size_t off = base + (size_t)t * E_DIM;
        yh[off] = __ushort_as_bfloat16((unsigned short)(bits >> 16));
        yl[off] = __float2bfloat16_rn(ys - __uint_as_float(bits & 0xFFFF0000u));
        float ww2 = pp + w;
        float p2  = fmaxf(ww2, kt);
        e1 = expf(ww2 - p2); e2 = expf(kt - p2);
        aa = e1 * aa + e2 * vt;
        bb = e1 * bb + e2;
        pp = p2;
    }
}

// ---------------------------------------------------------------------------
// Host orchestration
// ---------------------------------------------------------------------------
static void set_smem_attrs() {
    cudaFuncSetAttribute(gemm_bf<EPI_NONE>,   cudaFuncAttributeMaxDynamicSharedMemorySize, GEMM_SMEM);
    cudaFuncSetAttribute(gemm_bf<EPI_BIAS>,   cudaFuncAttributeMaxDynamicSharedMemorySize, GEMM_SMEM);
    cudaFuncSetAttribute(gemm_bf<EPI_RELUSQ>, cudaFuncAttributeMaxDynamicSharedMemorySize, GEMM_SMEM);
    cudaFuncSetAttribute(gemm_bf<EPI_ADD>,    cudaFuncAttributeMaxDynamicSharedMemorySize, GEMM_SMEM);
    cudaFuncSetAttribute(gemm_bf<EPI_CMIX>,   cudaFuncAttributeMaxDynamicSharedMemorySize, GEMM_SMEM);
}

extern "C" void kernel_launch(void* const* d_in, const int* in_sizes, int n_in,
                              void* d_out, int out_size)
{
    const float* inp    = (const float*)d_in[0];
    const float* W_in   = (const float*)d_in[1];
    const float* b_in   = (const float*)d_in[2];
    const float* ln0g   = (const float*)d_in[3];
    const float* ln0b   = (const float*)d_in[4];
    const float* l0ln1g = (const float*)d_in[5];
    const float* l0ln1b = (const float*)d_in[6];
    const float* l0ln2g = (const float*)d_in[7];
    const float* l0ln2b = (const float*)d_in[8];
    const float* l0cmk  = (const float*)d_in[9];
    const float* l0cmv  = (const float*)d_in[10];
    const float* l0cmr  = (const float*)d_in[11];
    const float* l0ffk  = (const float*)d_in[12];
    const float* l0ffv  = (const float*)d_in[13];
    const float* l0ffr  = (const float*)d_in[14];
    const float* tmk    = (const float*)d_in[15];
    const float* tmr    = (const float*)d_in[16];
    const float* tmo    = (const float*)d_in[17];
    const float* tmdec  = (const float*)d_in[18];
    const float* tmfst  = (const float*)d_in[19];
    const float* ln1g   = (const float*)d_in[20];
    const float* ln1b   = (const float*)d_in[21];
    const float* ln2g   = (const float*)d_in[22];
    const float* ln2b   = (const float*)d_in[23];
    const float* ffk    = (const float*)d_in[24];
    const float* ffv    = (const float*)d_in[25];
    const float* ffr    = (const float*)d_in[26];
    const float* outg   = (const float*)d_in[27];
    const float* outb   = (const float*)d_in[28];
    float* out = (float*)d_out;

    set_smem_attrs();

    __nv_bfloat16 *wh, *wl, *xnh, *xnl, *hbh, *hbl, *yh, *yl;
    float *res, *tmp, *kb, *rb, *st;
    cudaGetSymbolAddress((void**)&wh,  g_wh);
    cudaGetSymbolAddress((void**)&wl,  g_wl);
    cudaGetSymbolAddress((void**)&xnh, g_xnh);
    cudaGetSymbolAddress((void**)&xnl, g_xnl);
    cudaGetSymbolAddress((void**)&hbh, g_hbh);
    cudaGetSymbolAddress((void**)&hbl, g_hbl);
    cudaGetSymbolAddress((void**)&yh,  g_yh);
    cudaGetSymbolAddress((void**)&yl,  g_yl);
    cudaGetSymbolAddress((void**)&res, g_res);
    cudaGetSymbolAddress((void**)&tmp, g_tmp);
    cudaGetSymbolAddress((void**)&kb,  g_k);
    cudaGetSymbolAddress((void**)&rb,  g_r);
    cudaGetSymbolAddress((void**)&st,  g_st);

    // ---- pre-convert weights + inputs to bf16 h/l (vectorized, grid-stride) ----
    size_t off = 0;
    auto conv = [&](const float* src, size_t n) -> size_t {
        size_t o = off;
        int n8 = (int)(n / 8);
        int grid = (n8 + 255) / 256;
        if (grid > 4736) grid = 4736;
        convert_hl<<<grid, 256>>>((const float4*)src, (uint4*)(wh + o), (uint4*)(wl + o), n8);
        off += n;
        return o;
    };
    const size_t o_win  = conv(W_in,  (size_t)E_DIM * D_IN);
    const size_t o_cmk  = conv(l0cmk, (size_t)FOUR_E * E_DIM);
    const size_t o_cmv  = conv(l0cmv, (size_t)E_DIM * FOUR_E);
    const size_t o_cmr  = conv(l0cmr, (size_t)E_DIM * E_DIM);
    const size_t o_lffk = conv(l0ffk, (size_t)FOUR_E * E_DIM);
    const size_t o_lffv = conv(l0ffv, (size_t)E_DIM * FOUR_E);
    const size_t o_lffr = conv(l0ffr, (size_t)E_DIM * E_DIM);
    const size_t o_tmk  = conv(tmk, (size_t)NLAYER * E_DIM * E_DIM);
    const size_t o_tmr  = conv(tmr, (size_t)NLAYER * E_DIM * E_DIM);
    const size_t o_tmo  = conv(tmo, (size_t)NLAYER * E_DIM * E_DIM);
    const size_t o_ffk  = conv(ffk, (size_t)NLAYER * FOUR_E * E_DIM);
    const size_t o_ffv  = conv(ffv, (size_t)NLAYER * E_DIM * FOUR_E);
    const size_t o_ffr  = conv(ffr, (size_t)NLAYER * E_DIM * E_DIM);
    const size_t o_inp  = conv(inp, (size_t)BTOK * D_IN);

    const dim3 gE  (E_DIM  / TN, BTOK / TM);  // (4, 32) = 128 CTAs
    const dim3 g4E (FOUR_E / TN, BTOK / TM);  // (16, 32) = 512 CTAs
    const dim3 gWKV(E_DIM / 128, NCHUNK, BATCH);

    // x = inputs @ W_in^T + b_in ; res = LN(x, ln0)
    gemm_bf<EPI_BIAS><<<gE, GT, GEMM_SMEM>>>(wh + o_inp, wl + o_inp, wh + o_win, wl + o_win,
                                             tmp, BTOK, E_DIM, D_IN, b_in, nullptr, nullptr,
                                             nullptr, nullptr);
    ln_kernel<<<BTOK, 256>>>(tmp, res, nullptr, nullptr, ln0g, ln0b);

    auto cmix = [&](const float* lg, const float* lb,
                    size_t ok, size_t ov, size_t orr) {
        ln_kernel<<<BTOK, 256>>>(res, nullptr, xnh, xnl, lg, lb);
        gemm_bf<EPI_RELUSQ><<<g4E, GT, GEMM_SMEM>>>(xnh, xnl, wh + ok, wl + ok,
            nullptr, BTOK, FOUR_E, E_DIM, nullptr, nullptr, nullptr, hbh, hbl);
        gemm_bf<EPI_NONE><<<gE, GT, GEMM_SMEM>>>(xnh, xnl, wh + orr, wl + orr,
            rb, BTOK, E_DIM, E_DIM, nullptr, nullptr, nullptr, nullptr, nullptr);
        gemm_bf<EPI_CMIX><<<gE, GT, GEMM_SMEM>>>(hbh, hbl, wh + ov, wl + ov,
            res, BTOK, E_DIM, FOUR_E, nullptr, res, rb, nullptr, nullptr);
    };

    cmix(l0ln1g, l0ln1b, o_cmk, o_cmv, o_cmr);
    cmix(l0ln2g, l0ln2b, o_lffk, o_lffv, o_lffr);

    for (int l = 0; l < NLAYER; l++) {
        const size_t oEE = (size_t)l * E_DIM * E_DIM;
        const size_t o4E = (size_t)l * FOUR_E * E_DIM;
        const size_t oE  = (size_t)l * E_DIM;

        ln_kernel<<<BTOK, 256>>>(res, nullptr, xnh, xnl, ln1g + oE, ln1b + oE);
        gemm_bf<EPI_NONE><<<gE, GT, GEMM_SMEM>>>(xnh, xnl, wh + o_tmk + oEE, wl + o_tmk + oEE,
            kb, BTOK, E_DIM, E_DIM, nullptr, nullptr, nullptr, nullptr, nullptr);
        gemm_bf<EPI_NONE><<<gE, GT, GEMM_SMEM>>>(xnh, xnl, wh + o_tmr + oEE, wl + o_tmr + oEE,
            rb, BTOK, E_DIM, E_DIM, nullptr, nullptr, nullptr, nullptr, nullptr);
        wkv_pass1<<<gWKV, 128>>>(kb, rb, tmdec + oE, st);
        wkv_pass2<<<gWKV, 128>>>(kb, rb, tmdec + oE, tmfst + oE, st, yh, yl);
        gemm_bf<EPI_ADD><<<gE, GT, GEMM_SMEM>>>(yh, yl, wh + o_tmo + oEE, wl + o_tmo + oEE,
            res, BTOK, E_DIM, E_DIM, nullptr, res, nullptr, nullptr, nullptr);

        ln_kernel<<<BTOK, 256>>>(res, nullptr, xnh, xnl, ln2g + oE, ln2b + oE);
        gemm_bf<EPI_RELUSQ><<<g4E, GT, GEMM_SMEM>>>(xnh, xnl, wh + o_ffk + o4E, wl + o_ffk + o4E,
            nullptr, BTOK, FOUR_E, E_DIM, nullptr, nullptr, nullptr, hbh, hbl);
        gemm_bf<EPI_NONE><<<gE, GT, GEMM_SMEM>>>(xnh, xnl, wh + o_ffr + oEE, wl + o_ffr + oEE,
            rb, BTOK, E_DIM, E_DIM, nullptr, nullptr, nullptr, nullptr, nullptr);
        gemm_bf<EPI_CMIX><<<gE, GT, GEMM_SMEM>>>(hbh, hbl, wh + o_ffv + o4E, wl + o_ffv + o4E,
            res, BTOK, E_DIM, FOUR_E, nullptr, res, rb, nullptr, nullptr);
    }

    ln_kernel<<<BTOK, 256>>>(res, out, nullptr, nullptr, outg, outb);
}

// round 6
// speedup vs baseline: 1.1166x; 1.0739x over previous
#include <cuda_runtime.h>
#include <cuda_bf16.h>
#include <cstdint>
#include <math.h>

// ---------------------------------------------------------------------------
// RWKV forward. GEMMs: legacy mma.sync bf16 hi/lo 3-product split, fp32 accum.
// R6: product-pass MMA ordering (break acc RAW chains), warp tile 32x64,
// one sync per stage. Weights pre-converted to bf16 h/l.
// ---------------------------------------------------------------------------

#define E_DIM   1024
#define FOUR_E  4096
#define D_IN    512
#define BTOK    4096
#define T_LEN   1024
#define BATCH   4
#define NLAYER  11
#define NCHUNK  16
#define CHLEN   64

// ---------------- device-global scratch (no allocation allowed) ------------
#define WBUF_ELEMS 159907840ull
__device__ __nv_bfloat16 g_wh[WBUF_ELEMS];
__device__ __nv_bfloat16 g_wl[WBUF_ELEMS];

__device__ __nv_bfloat16 g_xnh[BTOK * E_DIM],  g_xnl[BTOK * E_DIM];
__device__ __nv_bfloat16 g_hbh[BTOK * FOUR_E], g_hbl[BTOK * FOUR_E];
__device__ __nv_bfloat16 g_yh [BTOK * E_DIM],  g_yl [BTOK * E_DIM];

__device__ float g_res[BTOK * E_DIM];
__device__ float g_tmp[BTOK * E_DIM];
__device__ float g_k  [BTOK * E_DIM];
__device__ float g_r  [BTOK * E_DIM];
__device__ float g_st [BATCH * NCHUNK * 3 * E_DIM];

// ---------------------------------------------------------------------------
// helpers
// ---------------------------------------------------------------------------
__device__ __forceinline__ uint32_t smem_u32(const void* p) {
    uint32_t a;
    asm("{ .reg .u64 t; cvta.to.shared.u64 t, %1; cvt.u32.u64 %0, t; }" : "=r"(a) : "l"(p));
    return a;
}
__device__ __forceinline__ void ldm_x4(uint32_t* r, uint32_t addr) {
    asm volatile("ldmatrix.sync.aligned.m8n8.x4.shared.b16 {%0,%1,%2,%3}, [%4];"
        : "=r"(r[0]), "=r"(r[1]), "=r"(r[2]), "=r"(r[3]) : "r"(addr));
}
__device__ __forceinline__ void mma_bf16(float* d, const uint32_t* a, uint32_t b0, uint32_t b1) {
    asm volatile("mma.sync.aligned.m16n8k16.row.col.f32.bf16.bf16.f32 "
        "{%0,%1,%2,%3}, {%4,%5,%6,%7}, {%8,%9}, {%0,%1,%2,%3};"
        : "+f"(d[0]), "+f"(d[1]), "+f"(d[2]), "+f"(d[3])
        : "r"(a[0]), "r"(a[1]), "r"(a[2]), "r"(a[3]), "r"(b0), "r"(b1));
}
__device__ __forceinline__ void cp16(uint32_t s, const void* g) {
    asm volatile("cp.async.cg.shared.global [%0], [%1], 16;" :: "r"(s), "l"(g));
}
__device__ __forceinline__ void cp_commit() {
    asm volatile("cp.async.commit_group;" ::: "memory");
}
template <int N> __device__ __forceinline__ void cp_wait() {
    asm volatile("cp.async.wait_group %0;" :: "n"(N) : "memory");
}
// float2 -> truncated-hi bf16x2 + residual-lo bf16x2
__device__ __forceinline__ void split2(float2 v, uint32_t& h, uint32_t& l) {
    uint32_t bx = __float_as_uint(v.x), by = __float_as_uint(v.y);
    h = __byte_perm(bx, by, 0x7632);
    float lx = v.x - __uint_as_float(bx & 0xFFFF0000u);
    float ly = v.y - __uint_as_float(by & 0xFFFF0000u);
    asm("cvt.rn.bf16x2.f32 %0, %1, %2;" : "=r"(l) : "f"(ly), "f"(lx));
}
__device__ __forceinline__ void split4(float4 v, uint32_t& h01, uint32_t& h23,
                                       uint32_t& l01, uint32_t& l23) {
    split2(make_float2(v.x, v.y), h01, l01);
    split2(make_float2(v.z, v.w), h23, l23);
}

// ---------------------------------------------------------------------------
// conversion: fp32 -> (hi bf16 trunc, lo bf16 residual), 8 floats per iter
// ---------------------------------------------------------------------------
__global__ void convert_hl(const float4* __restrict__ src,
                           uint4* __restrict__ h, uint4* __restrict__ l, int n8)
{
    const int stride = gridDim.x * blockDim.x;
    for (int i = blockIdx.x * blockDim.x + threadIdx.x; i < n8; i += stride) {
        float4 v0 = src[2 * i];
        float4 v1 = src[2 * i + 1];
        uint4 hh, ll;
        split4(v0, hh.x, hh.y, ll.x, ll.y);
        split4(v1, hh.z, hh.w, ll.z, ll.w);
        h[i] = hh;
        l[i] = ll;
    }
}

// ---------------------------------------------------------------------------
// GEMM: C[M,N] = A[M,K] @ W[N,K]^T, bf16 h/l inputs, fp32 epilogue.
// CTA 128x256x32, 512 threads (16 warps: 4m x 4n), warp tile 32x64, 3 stages.
// MMAs issued in product passes to keep 8 independent accumulator chains.
// ---------------------------------------------------------------------------
#define TM 128
#define TN 256
#define TK 32
#define GT 512
#define STAGES 3

#define ROWB   80
#define OFF_AH 0
#define OFF_AL (128 * ROWB)
#define OFF_BH (2 * 128 * ROWB)
#define OFF_BL (2 * 128 * ROWB + 256 * ROWB)
#define STAGE_SZ (2 * 128 * ROWB + 2 * 256 * ROWB)   // 61440
#define GEMM_SMEM (STAGES * STAGE_SZ)                // 184320

#define EPI_NONE   0
#define EPI_BIAS   1
#define EPI_RELUSQ 2
#define EPI_ADD    3
#define EPI_CMIX   4

template <int EPI>
__global__ __launch_bounds__(GT, 1)
void gemm_bf(const __nv_bfloat16* __restrict__ Ah, const __nv_bfloat16* __restrict__ Al,
             const __nv_bfloat16* __restrict__ Bh, const __nv_bfloat16* __restrict__ Bl,
             float* __restrict__ C, int M, int N, int K,
             const float* __restrict__ bias,
             const float* __restrict__ Cin,
             const float* __restrict__ Rg,
             __nv_bfloat16* __restrict__ Oh, __nv_bfloat16* __restrict__ Ol)
{
    extern __shared__ char smem[];
    const uint32_t sbase = smem_u32(smem);
    const int tid  = threadIdx.x;
    const int lane = tid & 31;
    const int wid  = tid >> 5;
    const int wm   = wid & 3;    // 4 warps in m (32 rows each)
    const int wn   = wid >> 2;   // 4 warps in n (64 cols each)
    const int bm   = blockIdx.y * TM;
    const int bn   = blockIdx.x * TN;

    const int lrow  = lane & 15;
    const int lchun = lane >> 4;

    float acc[2][8][4];   // [mt 16-row][nt 8-col][frag]
#pragma unroll
    for (int i = 0; i < 2; i++)
#pragma unroll
        for (int j = 0; j < 8; j++)
#pragma unroll
            for (int q = 0; q < 4; q++) acc[i][j][q] = 0.f;

    const int S = K / TK;

    auto issue = [&](int s, int buf) {
        const uint32_t sb = sbase + buf * STAGE_SZ;
        const int k0 = s * TK;
        // A (h+l): 128 rows x 4 segs of 16B -> 512 slots, 1 iter/thread
        {
            int row = tid >> 2, seg = tid & 3;
            uint32_t sa = sb + OFF_AH + row * ROWB + seg * 16;
            size_t go = (size_t)(bm + row) * K + k0 + seg * 8;
            cp16(sa, Ah + go);
            cp16(sa + (OFF_AL - OFF_AH), Al + go);
        }
        // B (h+l): 256 rows x 4 segs -> 1024 slots, 2 iters/thread
#pragma unroll
        for (int i = 0; i < 2; i++) {
            int idx = tid + i * GT;
            int row = idx >> 2, seg = idx & 3;
            uint32_t sa = sb + OFF_BH + row * ROWB + seg * 16;
            size_t go = (size_t)(bn + row) * K + k0 + seg * 8;
            cp16(sa, Bh + go);
            cp16(sa + (OFF_BL - OFF_BH), Bl + go);
        }
        cp_commit();
    };

    issue(0, 0);
    issue(1, 1);

    for (int s = 0; s < S; s++) {
        const int buf = s % STAGES;
        cp_wait<1>();
        __syncthreads();

        const uint32_t sb = sbase + buf * STAGE_SZ;
#pragma unroll
        for (int kk = 0; kk < 2; kk++) {
            const uint32_t koff = (uint32_t)((kk * 2 + lchun) * 16);
            // A fragments for this kk (2 m-tiles, h+l)
            uint32_t ah[2][4], al[2][4];
#pragma unroll
            for (int mt = 0; mt < 2; mt++) {
                uint32_t aa = sb + OFF_AH + (uint32_t)((wm * 32 + mt * 16 + lrow) * ROWB) + koff;
                ldm_x4(ah[mt], aa);
                ldm_x4(al[mt], aa + (OFF_AL - OFF_AH));
            }
            // process B tiles two at a time (register budget)
#pragma unroll
            for (int bg = 0; bg < 2; bg++) {
                uint32_t bh[2][4], bl[2][4];
#pragma unroll
                for (int bt = 0; bt < 2; bt++) {
                    uint32_t ba = sb + OFF_BH +
                        (uint32_t)((wn * 64 + (bg * 2 + bt) * 16 + lrow) * ROWB) + koff;
                    ldm_x4(bh[bt], ba);
                    ldm_x4(bl[bt], ba + (OFF_BL - OFF_BH));
                }
                // product passes: 8 independent accumulator chains per pass
#pragma unroll
                for (int mt = 0; mt < 2; mt++)
#pragma unroll
                    for (int bt = 0; bt < 2; bt++)
#pragma unroll
                        for (int j = 0; j < 2; j++)
                            mma_bf16(acc[mt][bg * 4 + bt * 2 + j], ah[mt], bh[bt][j], bh[bt][2 + j]);
#pragma unroll
                for (int mt = 0; mt < 2; mt++)
#pragma unroll
                    for (int bt = 0; bt < 2; bt++)
#pragma unroll
                        for (int j = 0; j < 2; j++)
                            mma_bf16(acc[mt][bg * 4 + bt * 2 + j], ah[mt], bl[bt][j], bl[bt][2 + j]);
#pragma unroll
                for (int mt = 0; mt < 2; mt++)
#pragma unroll
                    for (int bt = 0; bt < 2; bt++)
#pragma unroll
                        for (int j = 0; j < 2; j++)
                            mma_bf16(acc[mt][bg * 4 + bt * 2 + j], al[mt], bh[bt][j], bh[bt][2 + j]);
            }
        }
        if (s + 2 < S) issue(s + 2, (s + 2) % STAGES);
    }

    // epilogue
#pragma unroll
    for (int mt = 0; mt < 2; mt++)
#pragma unroll
        for (int nt = 0; nt < 8; nt++) {
            const int row0 = bm + wm * 32 + mt * 16 + (lane >> 2);
            const int col  = bn + wn * 64 + (nt >> 1) * 16 + (nt & 1) * 8 + (lane & 3) * 2;
#pragma unroll
            for (int h = 0; h < 2; h++) {
                const int r = row0 + h * 8;
                const size_t idx = (size_t)r * N + col;
                float2 v = make_float2(acc[mt][nt][2 * h + 0], acc[mt][nt][2 * h + 1]);
                if (EPI == EPI_BIAS) {
                    float2 bb = *reinterpret_cast<const float2*>(bias + col);
                    v.x += bb.x; v.y += bb.y;
                    *reinterpret_cast<float2*>(C + idx) = v;
                }
                if (EPI == EPI_NONE) {
                    *reinterpret_cast<float2*>(C + idx) = v;
                }
                if (EPI == EPI_RELUSQ) {
                    v.x = v.x > 0.f ? v.x * v.x : 0.f;
                    v.y = v.y > 0.f ? v.y * v.y : 0.f;
                    uint32_t hh, ll;
                    split2(v, hh, ll);
                    *reinterpret_cast<uint32_t*>(Oh + idx) = hh;
                    *reinterpret_cast<uint32_t*>(Ol + idx) = ll;
                }
                if (EPI == EPI_ADD) {
                    float2 ci = *reinterpret_cast<const float2*>(Cin + idx);
                    v.x += ci.x; v.y += ci.y;
                    *reinterpret_cast<float2*>(C + idx) = v;
                }
                if (EPI == EPI_CMIX) {
                    float2 ci = *reinterpret_cast<const float2*>(Cin + idx);
                    float2 rr = *reinterpret_cast<const float2*>(Rg + idx);
                    v.x = ci.x + v.x * (1.f / (1.f + expf(-rr.x)));
                    v.y = ci.y + v.y * (1.f / (1.f + expf(-rr.y)));
                    *reinterpret_cast<float2*>(C + idx) = v;
                }
            }
        }
}

// ---------------------------------------------------------------------------
// LayerNorm over E=1024; optional fp32 out and/or bf16 h/l out.
// ---------------------------------------------------------------------------
__global__ __launch_bounds__(256)
void ln_kernel(const float* __restrict__ x, float* __restrict__ o,
               __nv_bfloat16* __restrict__ oh, __nv_bfloat16* __restrict__ ol,
               const float* __restrict__ g, const float* __restrict__ b)
{
    __shared__ float sm[18];
    const int row = blockIdx.x;
    const int t   = threadIdx.x;
    float4 v = reinterpret_cast<const float4*>(x + (size_t)row * E_DIM)[t];
    float s  = v.x + v.y + v.z + v.w;
    float ss = v.x * v.x + v.y * v.y + v.z * v.z + v.w * v.w;
#pragma unroll
    for (int off = 16; off > 0; off >>= 1) {
        s  += __shfl_xor_sync(0xffffffffu, s, off);
        ss += __shfl_xor_sync(0xffffffffu, ss, off);
    }
    const int wp = t >> 5, lane = t & 31;
    if (lane == 0) { sm[wp] = s; sm[8 + wp] = ss; }
    __syncthreads();
    if (t < 32) {
        s  = (t < 8) ? sm[t]     : 0.f;
        ss = (t < 8) ? sm[8 + t] : 0.f;
#pragma unroll
        for (int off = 4; off > 0; off >>= 1) {
            s  += __shfl_xor_sync(0xffffffffu, s, off);
            ss += __shfl_xor_sync(0xffffffffu, ss, off);
        }
        if (t == 0) {
            float mean = s * (1.f / E_DIM);
            float var  = ss * (1.f / E_DIM) - mean * mean;
            sm[16] = mean;
            sm[17] = rsqrtf(var + 1e-5f);
        }
    }
    __syncthreads();
    const float mean = sm[16], inv = sm[17];
    float4 gg = reinterpret_cast<const float4*>(g)[t];
    float4 bb = reinterpret_cast<const float4*>(b)[t];
    float4 ov;
    ov.x = (v.x - mean) * inv * gg.x + bb.x;
    ov.y = (v.y - mean) * inv * gg.y + bb.y;
    ov.z = (v.z - mean) * inv * gg.z + bb.z;
    ov.w = (v.w - mean) * inv * gg.w + bb.w;
    if (o) reinterpret_cast<float4*>(o + (size_t)row * E_DIM)[t] = ov;
    if (oh) {
        uint32_t h01, h23, l01, l23;
        split4(ov, h01, h23, l01, l23);
        reinterpret_cast<uint2*>(oh + (size_t)row * E_DIM)[t] = make_uint2(h01, h23);
        reinterpret_cast<uint2*>(ol + (size_t)row * E_DIM)[t] = make_uint2(l01, l23);
    }
}

// ---------------------------------------------------------------------------
// WKV recurrence, exact chunked 2-pass scan. pass2 emits sigmoid(r)*wkv as
// bf16 h/l (input to the Wo GEMM).
// ---------------------------------------------------------------------------
__global__ __launch_bounds__(128)
void wkv_pass1(const float* __restrict__ k, const float* __restrict__ v,
               const float* __restrict__ decay, float* __restrict__ st)
{
    const int e = blockIdx.x * blockDim.x + threadIdx.x;
    const int c = blockIdx.y, b = blockIdx.z;
    const float w = -expf(decay[e]);
    float aa = 0.f, bb = 0.f, pp = -1e38f;
    const size_t base = ((size_t)b * T_LEN + (size_t)c * CHLEN) * E_DIM + e;
    const float* kp = k + base;
    const float* vp = v + base;
#pragma unroll 4
    for (int t = 0; t < CHLEN; t++) {
        float kt = kp[(size_t)t * E_DIM];
        float vt = vp[(size_t)t * E_DIM];
        float ww = pp + w;
        float p  = fmaxf(ww, kt);
        float e1 = expf(ww - p);
        float e2 = expf(kt - p);
        aa = e1 * aa + e2 * vt;
        bb = e1 * bb + e2;
        pp = p;
    }
    float* s = st + ((size_t)(b * NCHUNK + c) * 3) * E_DIM + e;
    s[0] = aa; s[E_DIM] = bb; s[2 * E_DIM] = pp;
}

__global__ __launch_bounds__(128)
void wkv_pass2(const float* __restrict__ k, const float* __restrict__ v,
               const float* __restrict__ decay, const float* __restrict__ first,
               const float* __restrict__ st,
               __nv_bfloat16* __restrict__ yh, __nv_bfloat16* __restrict__ yl)
{
    const int e = blockIdx.x * blockDim.x + threadIdx.x;
    const int c = blockIdx.y, b = blockIdx.z;
    const float w = -expf(decay[e]);
    const float u = first[e];
    float aa = 0.f, bb = 0.f, pp = -1e38f;
    for (int j = 0; j < c; j++) {
        const float* s = st + ((size_t)(b * NCHUNK + j) * 3) * E_DIM + e;
        float pd = pp + (float)CHLEN * w;
        float a2 = s[0], b2 = s[E_DIM], p2 = s[2 * E_DIM];
        float p  = fmaxf(pd, p2);
        float e1 = expf(pd - p), e2 = expf(p2 - p);
        aa = e1 * aa + e2 * a2;
        bb = e1 * bb + e2 * b2;
        pp = p;
    }
    const size_t base = ((size_t)b * T_LEN + (size_t)c * CHLEN) * E_DIM + e;
    const float* kp = k + base;
    const float* vp = v + base;
    for (int t = 0; t < CHLEN; t++) {
        float kt = kp[(size_t)t * E_DIM];
        float vt = vp[(size_t)t * E_DIM];   // v == r in this model
        float ww = u + kt;
        float p  = fmaxf(pp, ww);
        float e1 = expf(pp - p), e2 = expf(ww - p);
        float yt = (e1 * aa + e2 * vt) / (e1 * bb + e2);
        float ys = yt * (1.f / (1.f + expf(-vt)));
        uint32_t bits = __float_as_uint(ys);
        const size_t off = base + (size_t)t * E_DIM;
        yh[off] = __ushort_as_bfloat16((unsigned short)(bits >> 16));
        yl[off] = __float2bfloat16_rn(ys - __uint_as_float(bits & 0xFFFF0000u));
        float ww2 = pp + w;
        float p2  = fmaxf(ww2, kt);
        e1 = expf(ww2 - p2); e2 = expf(kt - p2);
        aa = e1 * aa + e2 * vt;
        bb = e1 * bb + e2;
        pp = p2;
    }
}

// ---------------------------------------------------------------------------
// Host orchestration
// ---------------------------------------------------------------------------
static void set_smem_attrs() {
    cudaFuncSetAttribute(gemm_bf<EPI_NONE>,   cudaFuncAttributeMaxDynamicSharedMemorySize, GEMM_SMEM);
    cudaFuncSetAttribute(gemm_bf<EPI_BIAS>,   cudaFuncAttributeMaxDynamicSharedMemorySize, GEMM_SMEM);
    cudaFuncSetAttribute(gemm_bf<EPI_RELUSQ>, cudaFuncAttributeMaxDynamicSharedMemorySize, GEMM_SMEM);
    cudaFuncSetAttribute(gemm_bf<EPI_ADD>,    cudaFuncAttributeMaxDynamicSharedMemorySize, GEMM_SMEM);
    cudaFuncSetAttribute(gemm_bf<EPI_CMIX>,   cudaFuncAttributeMaxDynamicSharedMemorySize, GEMM_SMEM);
}

extern "C" void kernel_launch(void* const* d_in, const int* in_sizes, int n_in,
                              void* d_out, int out_size)
{
    const float* inp    = (const float*)d_in[0];
    const float* W_in   = (const float*)d_in[1];
    const float* b_in   = (const float*)d_in[2];
    const float* ln0g   = (const float*)d_in[3];
    const float* ln0b   = (const float*)d_in[4];
    const float* l0ln1g = (const float*)d_in[5];
    const float* l0ln1b = (const float*)d_in[6];
    const float* l0ln2g = (const float*)d_in[7];
    const float* l0ln2b = (const float*)d_in[8];
    const float* l0cmk  = (const float*)d_in[9];
    const float* l0cmv  = (const float*)d_in[10];
    const float* l0cmr  = (const float*)d_in[11];
    const float* l0ffk  = (const float*)d_in[12];
    const float* l0ffv  = (const float*)d_in[13];
    const float* l0ffr  = (const float*)d_in[14];
    const float* tmk    = (const float*)d_in[15];
    const float* tmr    = (const float*)d_in[16];
    const float* tmo    = (const float*)d_in[17];
    const float* tmdec  = (const float*)d_in[18];
    const float* tmfst  = (const float*)d_in[19];
    const float* ln1g   = (const float*)d_in[20];
    const float* ln1b   = (const float*)d_in[21];
    const float* ln2g   = (const float*)d_in[22];
    const float* ln2b   = (const float*)d_in[23];
    const float* ffk    = (const float*)d_in[24];
    const float* ffv    = (const float*)d_in[25];
    const float* ffr    = (const float*)d_in[26];
    const float* outg   = (const float*)d_in[27];
    const float* outb   = (const float*)d_in[28];
    float* out = (float*)d_out;

    set_smem_attrs();

    __nv_bfloat16 *wh, *wl, *xnh, *xnl, *hbh, *hbl, *yh, *yl;
    float *res, *tmp, *kb, *rb, *st;
    cudaGetSymbolAddress((void**)&wh,  g_wh);
    cudaGetSymbolAddress((void**)&wl,  g_wl);
    cudaGetSymbolAddress((void**)&xnh, g_xnh);
    cudaGetSymbolAddress((void**)&xnl, g_xnl);
    cudaGetSymbolAddress((void**)&hbh, g_hbh);
    cudaGetSymbolAddress((void**)&hbl, g_hbl);
    cudaGetSymbolAddress((void**)&yh,  g_yh);
    cudaGetSymbolAddress((void**)&yl,  g_yl);
    cudaGetSymbolAddress((void**)&res, g_res);
    cudaGetSymbolAddress((void**)&tmp, g_tmp);
    cudaGetSymbolAddress((void**)&kb,  g_k);
    cudaGetSymbolAddress((void**)&rb,  g_r);
    cudaGetSymbolAddress((void**)&st,  g_st);

    // ---- pre-convert weights + inputs to bf16 h/l (vectorized, grid-stride) ----
    size_t off = 0;
    auto conv = [&](const float* src, size_t n) -> size_t {
        size_t o = off;
        int n8 = (int)(n / 8);
        int grid = (n8 + 255) / 256;
        if (grid > 4736) grid = 4736;
        convert_hl<<<grid, 256>>>((const float4*)src, (uint4*)(wh + o), (uint4*)(wl + o), n8);
        off += n;
        return o;
    };
    const size_t o_win  = conv(W_in,  (size_t)E_DIM * D_IN);
    const size_t o_cmk  = conv(l0cmk, (size_t)FOUR_E * E_DIM);
    const size_t o_cmv  = conv(l0cmv, (size_t)E_DIM * FOUR_E);
    const size_t o_cmr  = conv(l0cmr, (size_t)E_DIM * E_DIM);
    const size_t o_lffk = conv(l0ffk, (size_t)FOUR_E * E_DIM);
    const size_t o_lffv = conv(l0ffv, (size_t)E_DIM * FOUR_E);
    const size_t o_lffr = conv(l0ffr, (size_t)E_DIM * E_DIM);
    const size_t o_tmk  = conv(tmk, (size_t)NLAYER * E_DIM * E_DIM);
    const size_t o_tmr  = conv(tmr, (size_t)NLAYER * E_DIM * E_DIM);
    const size_t o_tmo  = conv(tmo, (size_t)NLAYER * E_DIM * E_DIM);
    const size_t o_ffk  = conv(ffk, (size_t)NLAYER * FOUR_E * E_DIM);
    const size_t o_ffv  = conv(ffv, (size_t)NLAYER * E_DIM * FOUR_E);
    const size_t o_ffr  = conv(ffr, (size_t)NLAYER * E_DIM * E_DIM);
    const size_t o_inp  = conv(inp, (size_t)BTOK * D_IN);

    const dim3 gE  (E_DIM  / TN, BTOK / TM);  // (4, 32) = 128 CTAs
    const dim3 g4E (FOUR_E / TN, BTOK / TM);  // (16, 32) = 512 CTAs
    const dim3 gWKV(E_DIM / 128, NCHUNK, BATCH);

    // x = inputs @ W_in^T + b_in ; res = LN(x, ln0)
    gemm_bf<EPI_BIAS><<<gE, GT, GEMM_SMEM>>>(wh + o_inp, wl + o_inp, wh + o_win, wl + o_win,
                                             tmp, BTOK, E_DIM, D_IN, b_in, nullptr, nullptr,
                                             nullptr, nullptr);
    ln_kernel<<<BTOK, 256>>>(tmp, res, nullptr, nullptr, ln0g, ln0b);

    auto cmix = [&](const float* lg, const float* lb,
                    size_t ok, size_t ov, size_t orr) {
        ln_kernel<<<BTOK, 256>>>(res, nullptr, xnh, xnl, lg, lb);
        gemm_bf<EPI_RELUSQ><<<g4E, GT, GEMM_SMEM>>>(xnh, xnl, wh + ok, wl + ok,
            nullptr, BTOK, FOUR_E, E_DIM, nullptr, nullptr, nullptr, hbh, hbl);
        gemm_bf<EPI_NONE><<<gE, GT, GEMM_SMEM>>>(xnh, xnl, wh + orr, wl + orr,
            rb, BTOK, E_DIM, E_DIM, nullptr, nullptr, nullptr, nullptr, nullptr);
        gemm_bf<EPI_CMIX><<<gE, GT, GEMM_SMEM>>>(hbh, hbl, wh + ov, wl + ov,
            res, BTOK, E_DIM, FOUR_E, nullptr, res, rb, nullptr, nullptr);
    };

    cmix(l0ln1g, l0ln1b, o_cmk, o_cmv, o_cmr);
    cmix(l0ln2g, l0ln2b, o_lffk, o_lffv, o_lffr);

    for (int l = 0; l < NLAYER; l++) {
        const size_t oEE = (size_t)l * E_DIM * E_DIM;
        const size_t o4E = (size_t)l * FOUR_E * E_DIM;
        const size_t oE  = (size_t)l * E_DIM;

        ln_kernel<<<BTOK, 256>>>(res, nullptr, xnh, xnl, ln1g + oE, ln1b + oE);
        gemm_bf<EPI_NONE><<<gE, GT, GEMM_SMEM>>>(xnh, xnl, wh + o_tmk + oEE, wl + o_tmk + oEE,
            kb, BTOK, E_DIM, E_DIM, nullptr, nullptr, nullptr, nullptr, nullptr);
        gemm_bf<EPI_NONE><<<gE, GT, GEMM_SMEM>>>(xnh, xnl, wh + o_tmr + oEE, wl + o_tmr + oEE,
            rb, BTOK, E_DIM, E_DIM, nullptr, nullptr, nullptr, nullptr, nullptr);
        wkv_pass1<<<gWKV, 128>>>(kb, rb, tmdec + oE, st);
        wkv_pass2<<<gWKV, 128>>>(kb, rb, tmdec + oE, tmfst + oE, st, yh, yl);
        gemm_bf<EPI_ADD><<<gE, GT, GEMM_SMEM>>>(yh, yl, wh + o_tmo + oEE, wl + o_tmo + oEE,
            res, BTOK, E_DIM, E_DIM, nullptr, res, nullptr, nullptr, nullptr);

        ln_kernel<<<BTOK, 256>>>(res, nullptr, xnh, xnl, ln2g + oE, ln2b + oE);
        gemm_bf<EPI_RELUSQ><<<g4E, GT, GEMM_SMEM>>>(xnh, xnl, wh + o_ffk + o4E, wl + o_ffk + o4E,
            nullptr, BTOK, FOUR_E, E_DIM, nullptr, nullptr, nullptr, hbh, hbl);
        gemm_bf<EPI_NONE><<<gE, GT, GEMM_SMEM>>>(xnh, xnl, wh + o_ffr + oEE, wl + o_ffr + oEE,
            rb, BTOK, E_DIM, E_DIM, nullptr, nullptr, nullptr, nullptr, nullptr);
        gemm_bf<EPI_CMIX><<<gE, GT, GEMM_SMEM>>>(hbh, hbl, wh + o_ffv + o4E, wl + o_ffv + o4E,
            res, BTOK, E_DIM, FOUR_E, nullptr, res, rb, nullptr, nullptr);
    }

    ln_kernel<<<BTOK, 256>>>(res, out, nullptr, nullptr, outg, outb);
}

// round 7
// speedup vs baseline: 1.5872x; 1.4214x over previous
#include <cuda_runtime.h>
#include <cuda_fp16.h>
#include <cstdint>
#include <math.h>

// ---------------------------------------------------------------------------
// RWKV forward. GEMMs: mma.sync fp16, 2-product split (A = Ah+Al exact, B =
// fp16(W) single). C = Ah*Bh + Al*Bh = A*Bh; only error is W fp16 rounding.
// Weights converted once per launch by a single job-table kernel.
// ---------------------------------------------------------------------------

#define E_DIM   1024
#define FOUR_E  4096
#define D_IN    512
#define BTOK    4096
#define T_LEN   1024
#define BATCH   4
#define NLAYER  11
#define NCHUNK  16
#define CHLEN   64

// ---------------- device-global scratch (no allocation allowed) ------------
#define WBUF_ELEMS 157810688ull
__device__ __half g_wf[WBUF_ELEMS];

__device__ __half g_inh[BTOK * D_IN],   g_inl[BTOK * D_IN];
__device__ __half g_xnh[BTOK * E_DIM],  g_xnl[BTOK * E_DIM];
__device__ __half g_hbh[BTOK * FOUR_E], g_hbl[BTOK * FOUR_E];
__device__ __half g_yh [BTOK * E_DIM],  g_yl [BTOK * E_DIM];

__device__ float g_res[BTOK * E_DIM];
__device__ float g_tmp[BTOK * E_DIM];
__device__ float g_k  [BTOK * E_DIM];
__device__ float g_r  [BTOK * E_DIM];
__device__ float g_st [BATCH * NCHUNK * 3 * E_DIM];

// ---------------------------------------------------------------------------
// helpers
// ---------------------------------------------------------------------------
__device__ __forceinline__ uint32_t smem_u32(const void* p) {
    uint32_t a;
    asm("{ .reg .u64 t; cvta.to.shared.u64 t, %1; cvt.u32.u64 %0, t; }" : "=r"(a) : "l"(p));
    return a;
}
__device__ __forceinline__ void ldm_x4(uint32_t* r, uint32_t addr) {
    asm volatile("ldmatrix.sync.aligned.m8n8.x4.shared.b16 {%0,%1,%2,%3}, [%4];"
        : "=r"(r[0]), "=r"(r[1]), "=r"(r[2]), "=r"(r[3]) : "r"(addr));
}
__device__ __forceinline__ void mma_f16(float* d, const uint32_t* a, uint32_t b0, uint32_t b1) {
    asm volatile("mma.sync.aligned.m16n8k16.row.col.f32.f16.f16.f32 "
        "{%0,%1,%2,%3}, {%4,%5,%6,%7}, {%8,%9}, {%0,%1,%2,%3};"
        : "+f"(d[0]), "+f"(d[1]), "+f"(d[2]), "+f"(d[3])
        : "r"(a[0]), "r"(a[1]), "r"(a[2]), "r"(a[3]), "r"(b0), "r"(b1));
}
__device__ __forceinline__ void cp16(uint32_t s, const void* g) {
    asm volatile("cp.async.cg.shared.global [%0], [%1], 16;" :: "r"(s), "l"(g));
}
__device__ __forceinline__ void cp_commit() {
    asm volatile("cp.async.commit_group;" ::: "memory");
}
template <int N> __device__ __forceinline__ void cp_wait() {
    asm volatile("cp.async.wait_group %0;" :: "n"(N) : "memory");
}
// float2 -> fp16x2 hi (rn) + fp16x2 lo (exact residual, rn)
__device__ __forceinline__ void splith2(float2 v, uint32_t& h, uint32_t& l) {
    __half2 hh = __floats2half2_rn(v.x, v.y);
    h = *reinterpret_cast<uint32_t*>(&hh);
    float2 b = __half22float2(hh);
    __half2 ll = __floats2half2_rn(v.x - b.x, v.y - b.y);
    l = *reinterpret_cast<uint32_t*>(&ll);
}
__device__ __forceinline__ uint32_t h2pack(float a, float b) {
    __half2 h = __floats2half2_rn(a, b);
    return *reinterpret_cast<uint32_t*>(&h);
}

// ---------------------------------------------------------------------------
// weight conversion: fp32 -> fp16, all tensors in ONE launch (job table)
// ---------------------------------------------------------------------------
#define NJOBS 13
struct ConvJobs {
    const float* src[NJOBS];
    unsigned long long n[NJOBS];     // element counts (multiples of 8)
    unsigned long long ofs[NJOBS];   // dst offsets (elements)
};

__global__ void convert_w(ConvJobs jobs, __half* __restrict__ dst)
{
    const int jid = blockIdx.y;
    const float4* src = reinterpret_cast<const float4*>(jobs.src[jid]);
    uint4* d = reinterpret_cast<uint4*>(dst + jobs.ofs[jid]);
    const long long n8 = (long long)(jobs.n[jid] >> 3);
    const long long stride = (long long)gridDim.x * blockDim.x;
    for (long long i = blockIdx.x * (long long)blockDim.x + threadIdx.x; i < n8; i += stride) {
        float4 a = src[2 * i];
        float4 b = src[2 * i + 1];
        uint4 o;
        o.x = h2pack(a.x, a.y); o.y = h2pack(a.z, a.w);
        o.z = h2pack(b.x, b.y); o.w = h2pack(b.z, b.w);
        d[i] = o;
    }
}

// fp32 -> fp16 h/l pair (for the GEMM A-side input tensor)
__global__ void convert_pair(const float4* __restrict__ src,
                             uint2* __restrict__ h, uint2* __restrict__ l, int n4)
{
    const int stride = gridDim.x * blockDim.x;
    for (int i = blockIdx.x * blockDim.x + threadIdx.x; i < n4; i += stride) {
        float4 v = src[i];
        uint2 hh, ll;
        splith2(make_float2(v.x, v.y), hh.x, ll.x);
        splith2(make_float2(v.z, v.w), hh.y, ll.y);
        h[i] = hh;
        l[i] = ll;
    }
}

// ---------------------------------------------------------------------------
// GEMM: C[M,N] = A[M,K] @ W[N,K]^T. A = fp16 h/l pair, B = fp16 single.
// CTA 128x256x32, 512 threads (16 warps: 4m x 4n), warp tile 32x64, 4 stages.
// C = Ah*Bh + Al*Bh, product-pass ordering (8 independent acc chains).
// ---------------------------------------------------------------------------
#define TM 128
#define TN 256
#define TK 32
#define GT 512
#define STAGES 4

#define ROWB   80
#define OFF_AH 0
#define OFF_AL (128 * ROWB)
#define OFF_B  (2 * 128 * ROWB)
#define STAGE_SZ (2 * 128 * ROWB + 256 * ROWB)   // 40960
#define GEMM_SMEM (STAGES * STAGE_SZ)            // 163840

#define EPI_NONE   0
#define EPI_BIAS   1
#define EPI_RELUSQ 2
#define EPI_ADD    3
#define EPI_CMIX   4

template <int EPI>
__global__ __launch_bounds__(GT, 1)
void gemm_f16(const __half* __restrict__ Ah, const __half* __restrict__ Al,
              const __half* __restrict__ Bh,
              float* __restrict__ C, int M, int N, int K,
              const float* __restrict__ bias,
              const float* __restrict__ Cin,
              const float* __restrict__ Rg,
              __half* __restrict__ Oh, __half* __restrict__ Ol)
{
    extern __shared__ char smem[];
    const uint32_t sbase = smem_u32(smem);
    const int tid  = threadIdx.x;
    const int lane = tid & 31;
    const int wid  = tid >> 5;
    const int wm   = wid & 3;    // 4 warps in m (32 rows each)
    const int wn   = wid >> 2;   // 4 warps in n (64 cols each)
    const int bm   = blockIdx.y * TM;
    const int bn   = blockIdx.x * TN;

    const int lrow  = lane & 15;
    const int lchun = lane >> 4;

    float acc[2][8][4];
#pragma unroll
    for (int i = 0; i < 2; i++)
#pragma unroll
        for (int j = 0; j < 8; j++)
#pragma unroll
            for (int q = 0; q < 4; q++) acc[i][j][q] = 0.f;

    const int S = K / TK;

    auto issue = [&](int s, int buf) {
        const uint32_t sb = sbase + buf * STAGE_SZ;
        const int k0 = s * TK;
        // A h + l: 128 rows x 4 segs of 16B = 512 slots, 1 iter/thread each
        {
            int row = tid >> 2, seg = tid & 3;
            uint32_t sa = sb + OFF_AH + row * ROWB + seg * 16;
            size_t go = (size_t)(bm + row) * K + k0 + seg * 8;
            cp16(sa, Ah + go);
            cp16(sa + (OFF_AL - OFF_AH), Al + go);
        }
        // B: 256 rows x 4 segs = 1024 slots, 2 iters/thread
#pragma unroll
        for (int i = 0; i < 2; i++) {
            int idx = tid + i * GT;
            int row = idx >> 2, seg = idx & 3;
            uint32_t sa = sb + OFF_B + row * ROWB + seg * 16;
            size_t go = (size_t)(bn + row) * K + k0 + seg * 8;
            cp16(sa, Bh + go);
        }
        cp_commit();
    };

    issue(0, 0);
    issue(1, 1);
    issue(2, 2);

    for (int s = 0; s < S; s++) {
        const int buf = s % STAGES;
        cp_wait<2>();
        __syncthreads();

        const uint32_t sb = sbase + buf * STAGE_SZ;
#pragma unroll
        for (int kk = 0; kk < 2; kk++) {
            const uint32_t koff = (uint32_t)((kk * 2 + lchun) * 16);
            uint32_t ah[2][4], al[2][4];
#pragma unroll
            for (int mt = 0; mt < 2; mt++) {
                uint32_t aa = sb + OFF_AH + (uint32_t)((wm * 32 + mt * 16 + lrow) * ROWB) + koff;
                ldm_x4(ah[mt], aa);
                ldm_x4(al[mt], aa + (OFF_AL - OFF_AH));
            }
#pragma unroll
            for (int bg = 0; bg < 2; bg++) {
                uint32_t bh[2][4];
#pragma unroll
                for (int bt = 0; bt < 2; bt++) {
                    uint32_t ba = sb + OFF_B +
                        (uint32_t)((wn * 64 + (bg * 2 + bt) * 16 + lrow) * ROWB) + koff;
                    ldm_x4(bh[bt], ba);
                }
                // product passes: 8 independent accumulator chains per pass
#pragma unroll
                for (int mt = 0; mt < 2; mt++)
#pragma unroll
                    for (int bt = 0; bt < 2; bt++)
#pragma unroll
                        for (int j = 0; j < 2; j++)
                            mma_f16(acc[mt][bg * 4 + bt * 2 + j], ah[mt], bh[bt][j], bh[bt][2 + j]);
#pragma unroll
                for (int mt = 0; mt < 2; mt++)
#pragma unroll
                    for (int bt = 0; bt < 2; bt++)
#pragma unroll
                        for (int j = 0; j < 2; j++)
                            mma_f16(acc[mt][bg * 4 + bt * 2 + j], al[mt], bh[bt][j], bh[bt][2 + j]);
            }
        }
        if (s + 3 < S) issue(s + 3, (s + 3) % STAGES);
    }

    // epilogue
#pragma unroll
    for (int mt = 0; mt < 2; mt++)
#pragma unroll
        for (int nt = 0; nt < 8; nt++) {
            const int row0 = bm + wm * 32 + mt * 16 + (lane >> 2);
            const int col  = bn + wn * 64 + (nt >> 1) * 16 + (nt & 1) * 8 + (lane & 3) * 2;
#pragma unroll
            for (int h = 0; h < 2; h++) {
                const int r = row0 + h * 8;
                const size_t idx = (size_t)r * N + col;
                float2 v = make_float2(acc[mt][nt][2 * h + 0], acc[mt][nt][2 * h + 1]);
                if (EPI == EPI_BIAS) {
                    float2 bb = *reinterpret_cast<const float2*>(bias + col);
                    v.x += bb.x; v.y += bb.y;
                    *reinterpret_cast<float2*>(C + idx) = v;
                }
                if (EPI == EPI_NONE) {
                    *reinterpret_cast<float2*>(C + idx) = v;
                }
                if (EPI == EPI_RELUSQ) {
                    v.x = v.x > 0.f ? v.x * v.x : 0.f;
                    v.y = v.y > 0.f ? v.y * v.y : 0.f;
                    uint32_t hh, ll;
                    splith2(v, hh, ll);
                    *reinterpret_cast<uint32_t*>(Oh + idx) = hh;
                    *reinterpret_cast<uint32_t*>(Ol + idx) = ll;
                }
                if (EPI == EPI_ADD) {
                    float2 ci = *reinterpret_cast<const float2*>(Cin + idx);
                    v.x += ci.x; v.y += ci.y;
                    *reinterpret_cast<float2*>(C + idx) = v;
                }
                if (EPI == EPI_CMIX) {
                    float2 ci = *reinterpret_cast<const float2*>(Cin + idx);
                    float2 rr = *reinterpret_cast<const float2*>(Rg + idx);
                    v.x = ci.x + v.x * (1.f / (1.f + expf(-rr.x)));
                    v.y = ci.y + v.y * (1.f / (1.f + expf(-rr.y)));
                    *reinterpret_cast<float2*>(C + idx) = v;
                }
            }
        }
}

// ---------------------------------------------------------------------------
// LayerNorm over E=1024; optional fp32 out and/or fp16 h/l out.
// ---------------------------------------------------------------------------
__global__ __launch_bounds__(256)
void ln_kernel(const float* __restrict__ x, float* __restrict__ o,
               __half* __restrict__ oh, __half* __restrict__ ol,
               const float* __restrict__ g, const float* __restrict__ b)
{
    __shared__ float sm[18];
    const int row = blockIdx.x;
    const int t   = threadIdx.x;
    float4 v = reinterpret_cast<const float4*>(x + (size_t)row * E_DIM)[t];
    float s  = v.x + v.y + v.z + v.w;
    float ss = v.x * v.x + v.y * v.y + v.z * v.z + v.w * v.w;
#pragma unroll
    for (int off = 16; off > 0; off >>= 1) {
        s  += __shfl_xor_sync(0xffffffffu, s, off);
        ss += __shfl_xor_sync(0xffffffffu, ss, off);
    }
    const int wp = t >> 5, lane = t & 31;
    if (lane == 0) { sm[wp] = s; sm[8 + wp] = ss; }
    __syncthreads();
    if (t < 32) {
        s  = (t < 8) ? sm[t]     : 0.f;
        ss = (t < 8) ? sm[8 + t] : 0.f;
#pragma unroll
        for (int off = 4; off > 0; off >>= 1) {
            s  += __shfl_xor_sync(0xffffffffu, s, off);
            ss += __shfl_xor_sync(0xffffffffu, ss, off);
        }
        if (t == 0) {
            float mean = s * (1.f / E_DIM);
            float var  = ss * (1.f / E_DIM) - mean * mean;
            sm[16] = mean;
            sm[17] = rsqrtf(var + 1e-5f);
        }
    }
    __syncthreads();
    const float mean = sm[16], inv = sm[17];
    float4 gg = reinterpret_cast<const float4*>(g)[t];
    float4 bb = reinterpret_cast<const float4*>(b)[t];
    float4 ov;
    ov.x = (v.x - mean) * inv * gg.x + bb.x;
    ov.y = (v.y - mean) * inv * gg.y + bb.y;
    ov.z = (v.z - mean) * inv * gg.z + bb.z;
    ov.w = (v.w - mean) * inv * gg.w + bb.w;
    if (o) reinterpret_cast<float4*>(o + (size_t)row * E_DIM)[t] = ov;
    if (oh) {
        uint2 hh, ll;
        splith2(make_float2(ov.x, ov.y), hh.x, ll.x);
        splith2(make_float2(ov.z, ov.w), hh.y, ll.y);
        reinterpret_cast<uint2*>(oh + (size_t)row * E_DIM)[t] = hh;
        reinterpret_cast<uint2*>(ol + (size_t)row * E_DIM)[t] = ll;
    }
}

// ---------------------------------------------------------------------------
// WKV recurrence, exact chunked 2-pass scan. pass2 emits sigmoid(r)*wkv as
// fp16 h/l (input to the Wo GEMM).
// ---------------------------------------------------------------------------
__global__ __launch_bounds__(128)
void wkv_pass1(const float* __restrict__ k, const float* __restrict__ v,
               const float* __restrict__ decay, float* __restrict__ st)
{
    const int e = blockIdx.x * blockDim.x + threadIdx.x;
    const int c = blockIdx.y, b = blockIdx.z;
    const float w = -expf(decay[e]);
    float aa = 0.f, bb = 0.f, pp = -1e38f;
    const size_t base = ((size_t)b * T_LEN + (size_t)c * CHLEN) * E_DIM + e;
    const float* kp = k + base;
    const float* vp = v + base;
#pragma unroll 4
    for (int t = 0; t < CHLEN; t++) {
        float kt = kp[(size_t)t * E_DIM];
        float vt = vp[(size_t)t * E_DIM];
        float ww = pp + w;
        float p  = fmaxf(ww, kt);
        float e1 = expf(ww - p);
        float e2 = expf(kt - p);
        aa = e1 * aa + e2 * vt;
        bb = e1 * bb + e2;
        pp = p;
    }
    float* s = st + ((size_t)(b * NCHUNK + c) * 3) * E_DIM + e;
    s[0] = aa; s[E_DIM] = bb; s[2 * E_DIM] = pp;
}

__global__ __launch_bounds__(128)
void wkv_pass2(const float* __restrict__ k, const float* __restrict__ v,
               const float* __restrict__ decay, const float* __restrict__ first,
               const float* __restrict__ st,
               __half* __restrict__ yh, __half* __restrict__ yl)
{
    const int e = blockIdx.x * blockDim.x + threadIdx.x;
    const int c = blockIdx.y, b = blockIdx.z;
    const float w = -expf(decay[e]);
    const float u = first[e];
    float aa = 0.f, bb = 0.f, pp = -1e38f;
    for (int j = 0; j < c; j++) {
        const float* s = st + ((size_t)(b * NCHUNK + j) * 3) * E_DIM + e;
        float pd = pp + (float)CHLEN * w;
        float a2 = s[0], b2 = s[E_DIM], p2 = s[2 * E_DIM];
        float p  = fmaxf(pd, p2);
        float e1 = expf(pd - p), e2 = expf(p2 - p);
        aa = e1 * aa + e2 * a2;
        bb = e1 * bb + e2 * b2;
        pp = p;
    }
    const size_t base = ((size_t)b * T_LEN + (size_t)c * CHLEN) * E_DIM + e;
    const float* kp = k + base;
    const float* vp = v + base;
    for (int t = 0; t < CHLEN; t++) {
        float kt = kp[(size_t)t * E_DIM];
        float vt = vp[(size_t)t * E_DIM];   // v == r in this model
        float ww = u + kt;
        float p  = fmaxf(pp, ww);
        float e1 = expf(pp - p), e2 = expf(ww - p);
        float yt = (e1 * aa + e2 * vt) / (e1 * bb + e2);
        float ys = yt * (1.f / (1.f + expf(-vt)));
        const size_t off = base + (size_t)t * E_DIM;
        __half hi = __float2half_rn(ys);
        yh[off] = hi;
        yl[off] = __float2half_rn(ys - __half2float(hi));
        float ww2 = pp + w;
        float p2  = fmaxf(ww2, kt);
        e1 = expf(ww2 - p2); e2 = expf(kt - p2);
        aa = e1 * aa + e2 * vt;
        bb = e1 * bb + e2;
        pp = p2;
    }
}

// ---------------------------------------------------------------------------
// Host orchestration
// ---------------------------------------------------------------------------
static void set_smem_attrs() {
    cudaFuncSetAttribute(gemm_f16<EPI_NONE>,   cudaFuncAttributeMaxDynamicSharedMemorySize, GEMM_SMEM);
    cudaFuncSetAttribute(gemm_f16<EPI_BIAS>,   cudaFuncAttributeMaxDynamicSharedMemorySize, GEMM_SMEM);
    cudaFuncSetAttribute(gemm_f16<EPI_RELUSQ>, cudaFuncAttributeMaxDynamicSharedMemorySize, GEMM_SMEM);
    cudaFuncSetAttribute(gemm_f16<EPI_ADD>,    cudaFuncAttributeMaxDynamicSharedMemorySize, GEMM_SMEM);
    cudaFuncSetAttribute(gemm_f16<EPI_CMIX>,   cudaFuncAttributeMaxDynamicSharedMemorySize, GEMM_SMEM);
}

extern "C" void kernel_launch(void* const* d_in, const int* in_sizes, int n_in,
                              void* d_out, int out_size)
{
    const float* inp    = (const float*)d_in[0];
    const float* W_in   = (const float*)d_in[1];
    const float* b_in   = (const float*)d_in[2];
    const float* ln0g   = (const float*)d_in[3];
    const float* ln0b   = (const float*)d_in[4];
    const float* l0ln1g = (const float*)d_in[5];
    const float* l0ln1b = (const float*)d_in[6];
    const float* l0ln2g = (const float*)d_in[7];
    const float* l0ln2b = (const float*)d_in[8];
    const float* l0cmk  = (const float*)d_in[9];
    const float* l0cmv  = (const float*)d_in[10];
    const float* l0cmr  = (const float*)d_in[11];
    const float* l0ffk  = (const float*)d_in[12];
    const float* l0ffv  = (const float*)d_in[13];
    const float* l0ffr  = (const float*)d_in[14];
    const float* tmk    = (const float*)d_in[15];
    const float* tmr    = (const float*)d_in[16];
    const float* tmo    = (const float*)d_in[17];
    const float* tmdec  = (const float*)d_in[18];
    const float* tmfst  = (const float*)d_in[19];
    const float* ln1g   = (const float*)d_in[20];
    const float* ln1b   = (const float*)d_in[21];
    const float* ln2g   = (const float*)d_in[22];
    const float* ln2b   = (const float*)d_in[23];
    const float* ffk    = (const float*)d_in[24];
    const float* ffv    = (const float*)d_in[25];
    const float* ffr    = (const float*)d_in[26];
    const float* outg   = (const float*)d_in[27];
    const float* outb   = (const float*)d_in[28];
    float* out = (float*)d_out;

    set_smem_attrs();

    __half *wf, *inh, *inl, *xnh, *xnl, *hbh, *hbl, *yh, *yl;
    float *res, *tmp, *kb, *rb, *st;
    cudaGetSymbolAddress((void**)&wf,  g_wf);
    cudaGetSymbolAddress((void**)&inh, g_inh);
    cudaGetSymbolAddress((void**)&inl, g_inl);
    cudaGetSymbolAddress((void**)&xnh, g_xnh);
    cudaGetSymbolAddress((void**)&xnl, g_xnl);
    cudaGetSymbolAddress((void**)&hbh, g_hbh);
    cudaGetSymbolAddress((void**)&hbl, g_hbl);
    cudaGetSymbolAddress((void**)&yh,  g_yh);
    cudaGetSymbolAddress((void**)&yl,  g_yl);
    cudaGetSymbolAddress((void**)&res, g_res);
    cudaGetSymbolAddress((void**)&tmp, g_tmp);
    cudaGetSymbolAddress((void**)&kb,  g_k);
    cudaGetSymbolAddress((void**)&rb,  g_r);
    cudaGetSymbolAddress((void**)&st,  g_st);

    // ---- weight conversion: one job-table launch ----
    ConvJobs jobs;
    size_t off = 0;
    int ji = 0;
    auto addjob = [&](const float* src, size_t n) -> size_t {
        size_t o = off;
        jobs.src[ji] = src;
        jobs.n[ji]   = (unsigned long long)n;
        jobs.ofs[ji] = (unsigned long long)o;
        ji++;
        off += n;
        return o;
    };
    const size_t o_win  = addjob(W_in,  (size_t)E_DIM * D_IN);
    const size_t o_cmk  = addjob(l0cmk, (size_t)FOUR_E * E_DIM);
    const size_t o_cmv  = addjob(l0cmv, (size_t)E_DIM * FOUR_E);
    const size_t o_cmr  = addjob(l0cmr, (size_t)E_DIM * E_DIM);
    const size_t o_lffk = addjob(l0ffk, (size_t)FOUR_E * E_DIM);
    const size_t o_lffv = addjob(l0ffv, (size_t)E_DIM * FOUR_E);
    const size_t o_lffr = addjob(l0ffr, (size_t)E_DIM * E_DIM);
    const size_t o_tmk  = addjob(tmk, (size_t)NLAYER * E_DIM * E_DIM);
    const size_t o_tmr  = addjob(tmr, (size_t)NLAYER * E_DIM * E_DIM);
    const size_t o_tmo  = addjob(tmo, (size_t)NLAYER * E_DIM * E_DIM);
    const size_t o_ffk  = addjob(ffk, (size_t)NLAYER * FOUR_E * E_DIM);
    const size_t o_ffv  = addjob(ffv, (size_t)NLAYER * E_DIM * FOUR_E);
    const size_t o_ffr  = addjob(ffr, (size_t)NLAYER * E_DIM * E_DIM);
    convert_w<<<dim3(1184, NJOBS), 256>>>(jobs, wf);                              // launch 0
    convert_pair<<<1024, 256>>>((const float4*)inp, (uint2*)inh, (uint2*)inl,
                                (int)((size_t)BTOK * D_IN / 4));                  // launch 1

    const dim3 gE  (E_DIM  / TN, BTOK / TM);  // (4, 32) = 128 CTAs
    const dim3 g4E (FOUR_E / TN, BTOK / TM);  // (16, 32) = 512 CTAs
    const dim3 gWKV(E_DIM / 128, NCHUNK, BATCH);

    // x = inputs @ W_in^T + b_in ; res = LN(x, ln0)
    gemm_f16<EPI_BIAS><<<gE, GT, GEMM_SMEM>>>(inh, inl, wf + o_win,
        tmp, BTOK, E_DIM, D_IN, b_in, nullptr, nullptr, nullptr, nullptr);        // launch 2
    ln_kernel<<<BTOK, 256>>>(tmp, res, nullptr, nullptr, ln0g, ln0b);             // launch 3

    auto cmix = [&](const float* lg, const float* lb,
                    size_t ok, size_t ov, size_t orr) {
        ln_kernel<<<BTOK, 256>>>(res, nullptr, xnh, xnl, lg, lb);
        gemm_f16<EPI_RELUSQ><<<g4E, GT, GEMM_SMEM>>>(xnh, xnl, wf + ok,
            nullptr, BTOK, FOUR_E, E_DIM, nullptr, nullptr, nullptr, hbh, hbl);
        gemm_f16<EPI_NONE><<<gE, GT, GEMM_SMEM>>>(xnh, xnl, wf + orr,
            rb, BTOK, E_DIM, E_DIM, nullptr, nullptr, nullptr, nullptr, nullptr);
        gemm_f16<EPI_CMIX><<<gE, GT, GEMM_SMEM>>>(hbh, hbl, wf + ov,
            res, BTOK, E_DIM, FOUR_E, nullptr, res, rb, nullptr, nullptr);
    };

    cmix(l0ln1g, l0ln1b, o_cmk, o_cmv, o_cmr);      // launches 4..7 (5 = big 4E GEMM)
    cmix(l0ln2g, l0ln2b, o_lffk, o_lffv, o_lffr);

    for (int l = 0; l < NLAYER; l++) {
        const size_t oEE = (size_t)l * E_DIM * E_DIM;
        const size_t o4E = (size_t)l * FOUR_E * E_DIM;
        const size_t oE  = (size_t)l * E_DIM;

        ln_kernel<<<BTOK, 256>>>(res, nullptr, xnh, xnl, ln1g + oE, ln1b + oE);
        gemm_f16<EPI_NONE><<<gE, GT, GEMM_SMEM>>>(xnh, xnl, wf + o_tmk + oEE,
            kb, BTOK, E_DIM, E_DIM, nullptr, nullptr, nullptr, nullptr, nullptr);
        gemm_f16<EPI_NONE><<<gE, GT, GEMM_SMEM>>>(xnh, xnl, wf + o_tmr + oEE,
            rb, BTOK, E_DIM, E_DIM, nullptr, nullptr, nullptr, nullptr, nullptr);
        wkv_pass1<<<gWKV, 128>>>(kb, rb, tmdec + oE, st);
        wkv_pass2<<<gWKV, 128>>>(kb, rb, tmdec + oE, tmfst + oE, st, yh, yl);
        gemm_f16<EPI_ADD><<<gE, GT, GEMM_SMEM>>>(yh, yl, wf + o_tmo + oEE,
            res, BTOK, E_DIM, E_DIM, nullptr, res, nullptr, nullptr, nullptr);

        ln_kernel<<<BTOK, 256>>>(res, nullptr, xnh, xnl, ln2g + oE, ln2b + oE);
        gemm_f16<EPI_RELUSQ><<<g4E, GT, GEMM_SMEM>>>(xnh, xnl, wf + o_ffk + o4E,
            nullptr, BTOK, FOUR_E, E_DIM, nullptr, nullptr, nullptr, hbh, hbl);
        gemm_f16<EPI_NONE><<<gE, GT, GEMM_SMEM>>>(xnh, xnl, wf + o_ffr + oEE,
            rb, BTOK, E_DIM, E_DIM, nullptr, nullptr, nullptr, nullptr, nullptr);
        gemm_f16<EPI_CMIX><<<gE, GT, GEMM_SMEM>>>(hbh, hbl, wf + o_ffv + o4E,
            res, BTOK, E_DIM, FOUR_E, nullptr, res, rb, nullptr, nullptr);
    }

    ln_kernel<<<BTOK, 256>>>(res, out, nullptr, nullptr, outg, outb);
}